// round 5
// baseline (speedup 1.0000x reference)
#include <cuda_runtime.h>
#include <cuda_fp16.h>
#include <math.h>

// Problem-shape scratch (allocation-free rule: __device__ globals).
#define NMAX 50048
#define EMAX 1700000
#define SCAN_BLK 1024
#define MAX_SBLKS ((NMAX + SCAN_BLK - 1) / SCAN_BLK)

__device__ int    g_cnt[NMAX];
__device__ int    g_off[NMAX + 1];
__device__ int    g_cursor[NMAX];
__device__ int    g_bsum[MAX_SBLKS + 1];
__device__ float  g_dinv[NMAX];
__device__ float  g_a1[NMAX];        // A_norm * ones
__device__ int    g_eidx[EMAX];
__device__ float  g_ew[EMAX];
__device__ float  g_bufA[6500000];   // N x 128 fp32 scratch
__device__ float  g_bufB[6500000];   // N x 128 fp32 scratch
__device__ __half g_hA[6500000];     // N x 128 half scratch
__device__ __half g_hB[6500000];     // N x 128 half scratch
__device__ float  g_Wc[128 * 128];   // packed [W_mean | W_lv]
__device__ float  g_bc[128];         // packed [b_mean | b_lv]
__device__ float  g_Wem[128 * 128];  // W_enc @ Wc
__device__ float  g_bem[128];        // b_enc @ Wc
__device__ float  g_Wdd[64 * 128];   // W_d1 @ W_d2
__device__ float  g_bdd[128];        // b_d1 @ W_d2
__device__ float  g_zero[128];       // stays zero

// ---------------------------------------------------------------------------
// f32x2 packed-FMA helpers (FFMA2 — only reachable via PTX fma.rn.f32x2)
// ---------------------------------------------------------------------------
typedef unsigned long long u64;
__device__ __forceinline__ u64 bcast2(float s) {
    u64 r; asm("mov.b64 %0, {%1, %1};" : "=l"(r) : "f"(s)); return r;
}
__device__ __forceinline__ u64 pack2(float lo, float hi) {
    u64 r; asm("mov.b64 %0, {%1, %2};" : "=l"(r) : "f"(lo), "f"(hi)); return r;
}
__device__ __forceinline__ float2 unpack2(u64 v) {
    float2 f; asm("mov.b64 {%0, %1}, %2;" : "=f"(f.x), "=f"(f.y) : "l"(v)); return f;
}
__device__ __forceinline__ void fmaa2(u64& acc, u64 a, u64 b) {
    asm("fma.rn.f32x2 %0, %1, %2, %0;" : "+l"(acc) : "l"(a), "l"(b));
}

// ---------------------------------------------------------------------------
// CSR build
// ---------------------------------------------------------------------------
__global__ void k_zero_cnt(int n) {
    int i = blockIdx.x * blockDim.x + threadIdx.x;
    if (i < n) g_cnt[i] = 0;
}

__global__ void k_count(const int* __restrict__ dst, int E) {
    int i = blockIdx.x * blockDim.x + threadIdx.x;
    if (i < E) atomicAdd(&g_cnt[dst[i]], 1);
}

__global__ void k_dinv(int n) {
    int i = blockIdx.x * blockDim.x + threadIdx.x;
    if (i < n) g_dinv[i] = rsqrtf((float)g_cnt[i] + 1.0f);
}

__global__ void k_scan_local(int n) {
    int b = blockIdx.x;
    int t = threadIdx.x;          // 256 threads
    int lane = t & 31, wid = t >> 5;
    int idx = b * SCAN_BLK + t * 4;
    int v0 = (idx + 0 < n) ? g_cnt[idx + 0] : 0;
    int v1 = (idx + 1 < n) ? g_cnt[idx + 1] : 0;
    int v2 = (idx + 2 < n) ? g_cnt[idx + 2] : 0;
    int v3 = (idx + 3 < n) ? g_cnt[idx + 3] : 0;
    int s = v0 + v1 + v2 + v3;
    int pre = s;
    #pragma unroll
    for (int d = 1; d < 32; d <<= 1) {
        int t2 = __shfl_up_sync(0xffffffffu, pre, d);
        if (lane >= d) pre += t2;
    }
    __shared__ int wsum[8];
    __shared__ int wexcl[8];
    if (lane == 31) wsum[wid] = pre;
    __syncthreads();
    if (t == 0) {
        int acc = 0;
        #pragma unroll
        for (int i = 0; i < 8; i++) { wexcl[i] = acc; acc += wsum[i]; }
        g_bsum[b] = acc;
    }
    __syncthreads();
    int run = (pre - s) + wexcl[wid];
    if (idx + 0 < n) g_off[idx + 0] = run;  run += v0;
    if (idx + 1 < n) g_off[idx + 1] = run;  run += v1;
    if (idx + 2 < n) g_off[idx + 2] = run;  run += v2;
    if (idx + 3 < n) g_off[idx + 3] = run;
}

__global__ void k_scan_bsums(int nb, int n) {
    __shared__ int sh[64];
    int t = threadIdx.x;           // 64 threads, nb <= 49
    int v = (t < nb) ? g_bsum[t] : 0;
    sh[t] = v;
    __syncthreads();
    #pragma unroll
    for (int ofs = 1; ofs < 64; ofs <<= 1) {
        int x = (t >= ofs) ? sh[t - ofs] : 0;
        __syncthreads();
        sh[t] += x;
        __syncthreads();
    }
    if (t < nb) g_bsum[t] = sh[t] - v;
    if (t == 63) g_off[n] = sh[63];
}

__global__ void k_scan_add(int n) {
    int i = blockIdx.x * blockDim.x + threadIdx.x;
    if (i < n) {
        int o = g_off[i] + g_bsum[i >> 10];
        g_off[i] = o;
        g_cursor[i] = o;
    }
}

__global__ void k_fill(const int* __restrict__ src, const int* __restrict__ dst, int E) {
    int e = blockIdx.x * blockDim.x + threadIdx.x;
    if (e < E) {
        int s = src[e], d = dst[e];
        int p = atomicAdd(&g_cursor[d], 1);
        g_eidx[p] = s;
        g_ew[p] = g_dinv[s] * g_dinv[d];
    }
}

__global__ void k_a1(int n) {
    int w = (blockIdx.x * blockDim.x + threadIdx.x) >> 5;
    int lane = threadIdx.x & 31;
    if (w >= n) return;
    float acc = 0.0f;
    int p = g_off[w] + lane, end = g_off[w + 1];
    for (; p < end; p += 32) acc += g_ew[p];
    #pragma unroll
    for (int d = 16; d; d >>= 1) acc += __shfl_down_sync(0xffffffffu, acc, d);
    if (lane == 0) {
        float di = g_dinv[w];
        g_a1[w] = acc + di * di;
    }
}

// ---------------------------------------------------------------------------
// fp32 -> fp16 convert
// ---------------------------------------------------------------------------
__global__ void k_f2h(const float* __restrict__ X, __half* __restrict__ H, int n2) {
    int i = blockIdx.x * blockDim.x + threadIdx.x;
    if (i < n2) {
        float2 v = ((const float2*)X)[i];
        ((__half2*)H)[i] = __floats2half2_rn(v.x, v.y);
    }
}

// ---------------------------------------------------------------------------
// Aggregation Y = A_norm * X with half inputs, fp32 accumulation.
// 128 cols: lane handles 4 halves. OUTH: write half, else fp32.
// ---------------------------------------------------------------------------
__device__ __forceinline__ float4 h4_to_f4(float2 raw) {
    __half2 h0 = *reinterpret_cast<__half2*>(&raw.x);
    __half2 h1 = *reinterpret_cast<__half2*>(&raw.y);
    float2 f0 = __half22float2(h0);
    float2 f1 = __half22float2(h1);
    return make_float4(f0.x, f0.y, f1.x, f1.y);
}

template <bool OUTH>
__global__ void k_aggh128(const __half* __restrict__ X, void* __restrict__ Y, int n) {
    int w = (blockIdx.x * blockDim.x + threadIdx.x) >> 5;
    int lane = threadIdx.x & 31;
    if (w >= n) return;
    const float2* Xv = (const float2*)X;   // 4 halves per float2
    float di = g_dinv[w];
    float sw = di * di;
    float4 acc = h4_to_f4(Xv[(size_t)w * 32 + lane]);
    acc.x *= sw; acc.y *= sw; acc.z *= sw; acc.w *= sw;
    int p = g_off[w], end = g_off[w + 1];
    for (; p + 4 <= end; p += 4) {
        int   s0 = g_eidx[p + 0], s1 = g_eidx[p + 1], s2 = g_eidx[p + 2], s3 = g_eidx[p + 3];
        float w0 = g_ew[p + 0],   w1 = g_ew[p + 1],   w2 = g_ew[p + 2],   w3 = g_ew[p + 3];
        float4 a = h4_to_f4(Xv[(size_t)s0 * 32 + lane]);
        float4 b = h4_to_f4(Xv[(size_t)s1 * 32 + lane]);
        float4 c = h4_to_f4(Xv[(size_t)s2 * 32 + lane]);
        float4 d = h4_to_f4(Xv[(size_t)s3 * 32 + lane]);
        acc.x += w0 * a.x + w1 * b.x + w2 * c.x + w3 * d.x;
        acc.y += w0 * a.y + w1 * b.y + w2 * c.y + w3 * d.y;
        acc.z += w0 * a.z + w1 * b.z + w2 * c.z + w3 * d.z;
        acc.w += w0 * a.w + w1 * b.w + w2 * c.w + w3 * d.w;
    }
    for (; p < end; p++) {
        int s = g_eidx[p]; float w0 = g_ew[p];
        float4 a = h4_to_f4(Xv[(size_t)s * 32 + lane]);
        acc.x += w0 * a.x; acc.y += w0 * a.y; acc.z += w0 * a.z; acc.w += w0 * a.w;
    }
    if (OUTH) {
        float2 raw;
        *reinterpret_cast<__half2*>(&raw.x) = __floats2half2_rn(acc.x, acc.y);
        *reinterpret_cast<__half2*>(&raw.y) = __floats2half2_rn(acc.z, acc.w);
        ((float2*)Y)[(size_t)w * 32 + lane] = raw;
    } else {
        ((float4*)Y)[(size_t)w * 32 + lane] = acc;
    }
}

// 64 cols: lane handles 2 halves.
template <bool OUTH>
__global__ void k_aggh64(const __half* __restrict__ X, void* __restrict__ Y, int n) {
    int w = (blockIdx.x * blockDim.x + threadIdx.x) >> 5;
    int lane = threadIdx.x & 31;
    if (w >= n) return;
    const __half2* Xv = (const __half2*)X;
    float di = g_dinv[w];
    float sw = di * di;
    float2 acc = __half22float2(Xv[(size_t)w * 32 + lane]);
    acc.x *= sw; acc.y *= sw;
    int p = g_off[w], end = g_off[w + 1];
    for (; p + 4 <= end; p += 4) {
        int   s0 = g_eidx[p + 0], s1 = g_eidx[p + 1], s2 = g_eidx[p + 2], s3 = g_eidx[p + 3];
        float w0 = g_ew[p + 0],   w1 = g_ew[p + 1],   w2 = g_ew[p + 2],   w3 = g_ew[p + 3];
        float2 a = __half22float2(Xv[(size_t)s0 * 32 + lane]);
        float2 b = __half22float2(Xv[(size_t)s1 * 32 + lane]);
        float2 c = __half22float2(Xv[(size_t)s2 * 32 + lane]);
        float2 d = __half22float2(Xv[(size_t)s3 * 32 + lane]);
        acc.x += w0 * a.x + w1 * b.x + w2 * c.x + w3 * d.x;
        acc.y += w0 * a.y + w1 * b.y + w2 * c.y + w3 * d.y;
    }
    for (; p < end; p++) {
        int s = g_eidx[p]; float w0 = g_ew[p];
        float2 a = __half22float2(Xv[(size_t)s * 32 + lane]);
        acc.x += w0 * a.x; acc.y += w0 * a.y;
    }
    if (OUTH) {
        ((__half2*)Y)[(size_t)w * 32 + lane] = __floats2half2_rn(acc.x, acc.y);
    } else {
        ((float2*)Y)[(size_t)w * 32 + lane] = acc;
    }
}

// ---------------------------------------------------------------------------
// GEMMs
// ---------------------------------------------------------------------------
__device__ __forceinline__ void fma4(float4& acc, float s, const float4& v) {
    acc.x = fmaf(s, v.x, acc.x);
    acc.y = fmaf(s, v.y, acc.y);
    acc.z = fmaf(s, v.z, acc.z);
    acc.w = fmaf(s, v.w, acc.w);
}

// Plain scalar GEMM (tiny weight-combine precomputes only)
template <int KDIM>
__global__ void k_gemm2(const float* __restrict__ X, const float* __restrict__ W,
                        const float* __restrict__ b, float* __restrict__ Y, int M) {
    extern __shared__ float sm[];
    float* sW = sm;
    float* sb = sm + KDIM * 128;
    for (int idx = threadIdx.x; idx < KDIM * 32; idx += blockDim.x)
        ((float4*)sW)[idx] = ((const float4*)W)[idx];
    if (threadIdx.x < 128) sb[threadIdx.x] = b[threadIdx.x];
    __syncthreads();

    int lane = threadIdx.x & 31;
    int wg = (blockIdx.x * blockDim.x + threadIdx.x) >> 5;
    int nw = (gridDim.x * blockDim.x) >> 5;
    for (int r0 = wg * 2; r0 < M; r0 += nw * 2) {
        int r1 = r0 + 1;
        bool has1 = (r1 < M);
        const float* x0 = X + (size_t)r0 * KDIM;
        const float* x1 = X + (size_t)(has1 ? r1 : r0) * KDIM;
        float4 acc0 = ((const float4*)sb)[lane];
        float4 acc1 = acc0;
        #pragma unroll 8
        for (int k = 0; k < KDIM; k += 4) {
            float4 a = *(const float4*)(x0 + k);
            float4 c = *(const float4*)(x1 + k);
            float4 w0 = ((const float4*)(sW + (size_t)(k + 0) * 128))[lane];
            float4 w1 = ((const float4*)(sW + (size_t)(k + 1) * 128))[lane];
            float4 w2 = ((const float4*)(sW + (size_t)(k + 2) * 128))[lane];
            float4 w3 = ((const float4*)(sW + (size_t)(k + 3) * 128))[lane];
            fma4(acc0, a.x, w0); fma4(acc1, c.x, w0);
            fma4(acc0, a.y, w1); fma4(acc1, c.y, w1);
            fma4(acc0, a.z, w2); fma4(acc1, c.z, w2);
            fma4(acc0, a.w, w3); fma4(acc1, c.w, w3);
        }
        *(float4*)(Y + (size_t)r0 * 128 + lane * 4) = acc0;
        if (has1) *(float4*)(Y + (size_t)r1 * 128 + lane * 4) = acc1;
    }
}

// Production GEMM, f32x2 packed FMA: Y = X @ W + b + a1 (x) v
template <int KDIM>
__global__ void k_gemm_r1(const float* __restrict__ X, const float* __restrict__ W,
                          const float* __restrict__ b, const float* __restrict__ v,
                          float* __restrict__ Y, int M) {
    extern __shared__ float sm[];
    float* sW = sm;                 // KDIM * 128
    float* sb = sm + KDIM * 128;    // 128
    float* sv = sb + 128;           // 128
    for (int idx = threadIdx.x; idx < KDIM * 32; idx += blockDim.x)
        ((float4*)sW)[idx] = ((const float4*)W)[idx];
    if (threadIdx.x < 128) {
        sb[threadIdx.x] = b[threadIdx.x];
        sv[threadIdx.x] = v[threadIdx.x];
    }
    __syncthreads();

    const ulonglong2* sW2 = (const ulonglong2*)sW;
    int lane = threadIdx.x & 31;
    int wg = (blockIdx.x * blockDim.x + threadIdx.x) >> 5;
    int nw = (gridDim.x * blockDim.x) >> 5;
    for (int r0 = wg * 2; r0 < M; r0 += nw * 2) {
        int r1 = r0 + 1;
        bool has1 = (r1 < M);
        const float* x0 = X + (size_t)r0 * KDIM;
        const float* x1 = X + (size_t)(has1 ? r1 : r0) * KDIM;
        float4 bb = ((const float4*)sb)[lane];
        float4 vv = ((const float4*)sv)[lane];
        float a0 = g_a1[r0];
        float a1v = g_a1[has1 ? r1 : r0];
        u64 acc0l = pack2(fmaf(a0, vv.x, bb.x),  fmaf(a0, vv.y, bb.y));
        u64 acc0h = pack2(fmaf(a0, vv.z, bb.z),  fmaf(a0, vv.w, bb.w));
        u64 acc1l = pack2(fmaf(a1v, vv.x, bb.x), fmaf(a1v, vv.y, bb.y));
        u64 acc1h = pack2(fmaf(a1v, vv.z, bb.z), fmaf(a1v, vv.w, bb.w));
        #pragma unroll 8
        for (int k = 0; k < KDIM; k += 4) {
            float4 a = *(const float4*)(x0 + k);
            float4 c = *(const float4*)(x1 + k);
            ulonglong2 w0 = sW2[(size_t)(k + 0) * 32 + lane];
            ulonglong2 w1 = sW2[(size_t)(k + 1) * 32 + lane];
            ulonglong2 w2 = sW2[(size_t)(k + 2) * 32 + lane];
            ulonglong2 w3 = sW2[(size_t)(k + 3) * 32 + lane];
            u64 s;
            s = bcast2(a.x); fmaa2(acc0l, s, w0.x); fmaa2(acc0h, s, w0.y);
            s = bcast2(c.x); fmaa2(acc1l, s, w0.x); fmaa2(acc1h, s, w0.y);
            s = bcast2(a.y); fmaa2(acc0l, s, w1.x); fmaa2(acc0h, s, w1.y);
            s = bcast2(c.y); fmaa2(acc1l, s, w1.x); fmaa2(acc1h, s, w1.y);
            s = bcast2(a.z); fmaa2(acc0l, s, w2.x); fmaa2(acc0h, s, w2.y);
            s = bcast2(c.z); fmaa2(acc1l, s, w2.x); fmaa2(acc1h, s, w2.y);
            s = bcast2(a.w); fmaa2(acc0l, s, w3.x); fmaa2(acc0h, s, w3.y);
            s = bcast2(c.w); fmaa2(acc1l, s, w3.x); fmaa2(acc1h, s, w3.y);
        }
        float2 o0 = unpack2(acc0l), o1 = unpack2(acc0h);
        *(float4*)(Y + (size_t)r0 * 128 + lane * 4) = make_float4(o0.x, o0.y, o1.x, o1.y);
        if (has1) {
            float2 p0 = unpack2(acc1l), p1 = unpack2(acc1h);
            *(float4*)(Y + (size_t)r1 * 128 + lane * 4) = make_float4(p0.x, p0.y, p1.x, p1.y);
        }
    }
}

// Pack [W_mean | W_lv] into 128x128, same for bias.
__global__ void k_pack(const float* __restrict__ Wm, const float* __restrict__ Wl,
                       const float* __restrict__ bm, const float* __restrict__ bl) {
    int idx = blockIdx.x * blockDim.x + threadIdx.x;
    if (idx < 128 * 128) {
        int k = idx >> 7, c = idx & 127;
        g_Wc[idx] = (c < 64) ? Wm[k * 64 + c] : Wl[k * 64 + (c - 64)];
    }
    if (idx < 128) g_bc[idx] = (idx < 64) ? bm[idx] : bl[idx - 64];
}

// z = noise*exp(0.5*lv) + mean; split packed [mean|lv]; also emit half z.
__global__ void k_mlz(const float* __restrict__ ML, const float* __restrict__ noise,
                      float* __restrict__ z, float* __restrict__ m,
                      float* __restrict__ lv, __half* __restrict__ zh, int N) {
    int i = blockIdx.x * blockDim.x + threadIdx.x;  // over N*16 float4 groups
    if (i >= N * 16) return;
    int row = i >> 4, c4 = i & 15;
    float4 me  = *(const float4*)(ML + (size_t)row * 128 + c4 * 4);
    float4 lvv = *(const float4*)(ML + (size_t)row * 128 + 64 + c4 * 4);
    float4 nz  = ((const float4*)noise)[i];
    float4 zz;
    zz.x = fmaf(nz.x, expf(0.5f * lvv.x), me.x);
    zz.y = fmaf(nz.y, expf(0.5f * lvv.y), me.y);
    zz.z = fmaf(nz.z, expf(0.5f * lvv.z), me.z);
    zz.w = fmaf(nz.w, expf(0.5f * lvv.w), me.w);
    ((float4*)z)[i] = zz;
    ((float4*)m)[i] = me;
    ((float4*)lv)[i] = lvv;
    float2 raw;
    *reinterpret_cast<__half2*>(&raw.x) = __floats2half2_rn(zz.x, zz.y);
    *reinterpret_cast<__half2*>(&raw.y) = __floats2half2_rn(zz.z, zz.w);
    ((float2*)zh)[i] = raw;
}

// ---------------------------------------------------------------------------
extern "C" void kernel_launch(void* const* d_in, const int* in_sizes, int n_in,
                              void* d_out, int out_size) {
    const float* feature = (const float*)d_in[0];
    const int*   ei      = (const int*)d_in[1];
    const float* noise   = (const float*)d_in[2];
    const float* W_enc   = (const float*)d_in[3];
    const float* b_enc   = (const float*)d_in[4];
    const float* W_mean  = (const float*)d_in[5];
    const float* b_mean  = (const float*)d_in[6];
    const float* W_lv    = (const float*)d_in[7];
    const float* b_lv    = (const float*)d_in[8];
    const float* W_d1    = (const float*)d_in[9];
    const float* b_d1    = (const float*)d_in[10];
    const float* W_d2    = (const float*)d_in[11];
    const float* b_d2    = (const float*)d_in[12];

    int N = in_sizes[0] / 128;
    int E = in_sizes[1] / 2;
    const int* src = ei;
    const int* dst = ei + E;

    float* zout  = (float*)d_out;
    float* mout  = zout + (size_t)N * 64;
    float* lvout = mout + (size_t)N * 64;
    float* oout  = lvout + (size_t)N * 64;

    float *bufA, *bufB, *Wc, *bc, *Wem, *bem, *Wdd, *bdd, *zerov;
    __half *hA, *hB;
    cudaGetSymbolAddress((void**)&bufA, g_bufA);
    cudaGetSymbolAddress((void**)&bufB, g_bufB);
    cudaGetSymbolAddress((void**)&hA, g_hA);
    cudaGetSymbolAddress((void**)&hB, g_hB);
    cudaGetSymbolAddress((void**)&Wc, g_Wc);
    cudaGetSymbolAddress((void**)&bc, g_bc);
    cudaGetSymbolAddress((void**)&Wem, g_Wem);
    cudaGetSymbolAddress((void**)&bem, g_bem);
    cudaGetSymbolAddress((void**)&Wdd, g_Wdd);
    cudaGetSymbolAddress((void**)&bdd, g_bdd);
    cudaGetSymbolAddress((void**)&zerov, g_zero);

    const int smem128  = 128 * 128 * 4 + 512;
    const int smem128r = 128 * 128 * 4 + 1024;
    const int smem64r  = 64 * 128 * 4 + 1024;
    cudaFuncSetAttribute(k_gemm2<128>,   cudaFuncAttributeMaxDynamicSharedMemorySize, smem128);
    cudaFuncSetAttribute(k_gemm_r1<128>, cudaFuncAttributeMaxDynamicSharedMemorySize, smem128r);
    cudaFuncSetAttribute(k_gemm_r1<64>,  cudaFuncAttributeMaxDynamicSharedMemorySize, smem64r);

    int tb = 256;
    int nBlkN = (N + tb - 1) / tb;
    int nBlkE = (E + tb - 1) / tb;
    int nBlkW = (N * 32 + tb - 1) / tb;   // warp per node
    int nSBlks = (N + SCAN_BLK - 1) / SCAN_BLK;
    int gemmBlocks = 444;

    // --- CSR build ---
    k_zero_cnt<<<nBlkN, tb>>>(N);
    k_count<<<nBlkE, tb>>>(dst, E);
    k_dinv<<<nBlkN, tb>>>(N);
    k_scan_local<<<nSBlks, 256>>>(N);
    k_scan_bsums<<<1, 64>>>(nSBlks, N);
    k_scan_add<<<nBlkN, tb>>>(N);
    k_fill<<<nBlkE, tb>>>(src, dst, E);
    k_a1<<<nBlkW, tb>>>(N);

    // --- weight precomputes (tiny) ---
    k_pack<<<(128 * 128 + tb - 1) / tb, tb>>>(W_mean, W_lv, b_mean, b_lv);
    k_gemm2<128><<<8, tb, smem128>>>(W_enc, Wc, zerov, Wem, 128);   // We @ Wc
    k_gemm2<128><<<1, tb, smem128>>>(b_enc, Wc, zerov, bem, 1);     // be @ Wc
    k_gemm2<128><<<4, tb, smem128>>>(W_d1, W_d2, zerov, Wdd, 64);   // Wd1 @ Wd2
    k_gemm2<128><<<1, tb, smem128>>>(b_d1, W_d2, zerov, bdd, 1);    // bd1 @ Wd2

    // --- encoder collapsed: [mean|lv] = (A A f) Wem + a1 (x) bem + bc ---
    k_f2h<<<(N * 64 + tb - 1) / tb, tb>>>(feature, hA, N * 64);
    k_aggh128<true><<<nBlkW, tb>>>(hA, hB, N);
    k_aggh128<false><<<nBlkW, tb>>>(hB, bufA, N);
    k_gemm_r1<128><<<gemmBlocks, tb, smem128r>>>(bufA, Wem, bc, bem, bufB, N);
    k_mlz<<<(N * 16 + tb - 1) / tb, tb>>>(bufB, noise, zout, mout, lvout, hA, N);

    // --- decoder collapsed: out = (A A z) Wdd + a1 (x) bdd + bd2 ---
    k_aggh64<true><<<nBlkW, tb>>>(hA, hB, N);
    k_aggh64<false><<<nBlkW, tb>>>(hB, bufA, N);
    k_gemm_r1<64><<<gemmBlocks, tb, smem64r>>>(bufA, Wdd, b_d2, bdd, oout, N);
}

// round 6
// speedup vs baseline: 1.0020x; 1.0020x over previous
#include <cuda_runtime.h>
#include <cuda_fp16.h>
#include <math.h>

// Problem-shape scratch (allocation-free rule: __device__ globals).
#define NMAX 50048
#define EMAX 1700000
#define SCAN_BLK 1024
#define MAX_SBLKS ((NMAX + SCAN_BLK - 1) / SCAN_BLK)

__device__ int    g_cnt[NMAX];
__device__ int    g_off[NMAX + 1];
__device__ int    g_cursor[NMAX];
__device__ int    g_bsum[MAX_SBLKS + 1];
__device__ float  g_dinv[NMAX];
__device__ float  g_a1[NMAX];        // A_norm * ones
__device__ int    g_eidx[EMAX];
__device__ float  g_ew[EMAX];
__device__ float  g_bufA[6500000];   // N x 128 fp32 scratch
__device__ float  g_bufB[6500000];   // N x 128 fp32 scratch
__device__ __half g_hA[6500000];     // N x 128 half scratch
__device__ __half g_hB[6500000];     // N x 128 half scratch
__device__ float  g_Wc[128 * 128];   // packed [W_mean | W_lv]
__device__ float  g_bc[128];         // packed [b_mean | b_lv]
__device__ float  g_Wem[128 * 128];  // W_enc @ Wc
__device__ float  g_bem[128];        // b_enc @ Wc
__device__ float  g_Wdd[64 * 128];   // W_d1 @ W_d2
__device__ float  g_bdd[128];        // b_d1 @ W_d2
__device__ float  g_zero[128];       // stays zero

// ---------------------------------------------------------------------------
// f32x2 packed-FMA helpers (FFMA2 — only reachable via PTX fma.rn.f32x2)
// ---------------------------------------------------------------------------
typedef unsigned long long u64;
__device__ __forceinline__ u64 bcast2(float s) {
    u64 r; asm("mov.b64 %0, {%1, %1};" : "=l"(r) : "f"(s)); return r;
}
__device__ __forceinline__ u64 pack2(float lo, float hi) {
    u64 r; asm("mov.b64 %0, {%1, %2};" : "=l"(r) : "f"(lo), "f"(hi)); return r;
}
__device__ __forceinline__ float2 unpack2(u64 v) {
    float2 f; asm("mov.b64 {%0, %1}, %2;" : "=f"(f.x), "=f"(f.y) : "l"(v)); return f;
}
__device__ __forceinline__ void fmaa2(u64& acc, u64 a, u64 b) {
    asm("fma.rn.f32x2 %0, %1, %2, %0;" : "+l"(acc) : "l"(a), "l"(b));
}

// ---------------------------------------------------------------------------
// CSR build
// ---------------------------------------------------------------------------
__global__ void k_zero_cnt(int n) {
    int i = blockIdx.x * blockDim.x + threadIdx.x;
    if (i < n) g_cnt[i] = 0;
}

__global__ void k_count(const int* __restrict__ dst, int E) {
    int i = blockIdx.x * blockDim.x + threadIdx.x;
    if (i < E) atomicAdd(&g_cnt[dst[i]], 1);
}

__global__ void k_dinv(int n) {
    int i = blockIdx.x * blockDim.x + threadIdx.x;
    if (i < n) g_dinv[i] = rsqrtf((float)g_cnt[i] + 1.0f);
}

__global__ void k_scan_local(int n) {
    int b = blockIdx.x;
    int t = threadIdx.x;          // 256 threads
    int lane = t & 31, wid = t >> 5;
    int idx = b * SCAN_BLK + t * 4;
    int v0 = (idx + 0 < n) ? g_cnt[idx + 0] : 0;
    int v1 = (idx + 1 < n) ? g_cnt[idx + 1] : 0;
    int v2 = (idx + 2 < n) ? g_cnt[idx + 2] : 0;
    int v3 = (idx + 3 < n) ? g_cnt[idx + 3] : 0;
    int s = v0 + v1 + v2 + v3;
    int pre = s;
    #pragma unroll
    for (int d = 1; d < 32; d <<= 1) {
        int t2 = __shfl_up_sync(0xffffffffu, pre, d);
        if (lane >= d) pre += t2;
    }
    __shared__ int wsum[8];
    __shared__ int wexcl[8];
    if (lane == 31) wsum[wid] = pre;
    __syncthreads();
    if (t == 0) {
        int acc = 0;
        #pragma unroll
        for (int i = 0; i < 8; i++) { wexcl[i] = acc; acc += wsum[i]; }
        g_bsum[b] = acc;
    }
    __syncthreads();
    int run = (pre - s) + wexcl[wid];
    if (idx + 0 < n) g_off[idx + 0] = run;  run += v0;
    if (idx + 1 < n) g_off[idx + 1] = run;  run += v1;
    if (idx + 2 < n) g_off[idx + 2] = run;  run += v2;
    if (idx + 3 < n) g_off[idx + 3] = run;
}

__global__ void k_scan_bsums(int nb, int n) {
    __shared__ int sh[64];
    int t = threadIdx.x;           // 64 threads, nb <= 49
    int v = (t < nb) ? g_bsum[t] : 0;
    sh[t] = v;
    __syncthreads();
    #pragma unroll
    for (int ofs = 1; ofs < 64; ofs <<= 1) {
        int x = (t >= ofs) ? sh[t - ofs] : 0;
        __syncthreads();
        sh[t] += x;
        __syncthreads();
    }
    if (t < nb) g_bsum[t] = sh[t] - v;
    if (t == 63) g_off[n] = sh[63];
}

__global__ void k_scan_add(int n) {
    int i = blockIdx.x * blockDim.x + threadIdx.x;
    if (i < n) {
        int o = g_off[i] + g_bsum[i >> 10];
        g_off[i] = o;
        g_cursor[i] = o;
    }
}

__global__ void k_fill(const int* __restrict__ src, const int* __restrict__ dst, int E) {
    int e = blockIdx.x * blockDim.x + threadIdx.x;
    if (e < E) {
        int s = src[e], d = dst[e];
        int p = atomicAdd(&g_cursor[d], 1);
        g_eidx[p] = s;
        g_ew[p] = g_dinv[s] * g_dinv[d];
    }
}

__global__ void k_a1(int n) {
    int w = (blockIdx.x * blockDim.x + threadIdx.x) >> 5;
    int lane = threadIdx.x & 31;
    if (w >= n) return;
    float acc = 0.0f;
    int p = g_off[w] + lane, end = g_off[w + 1];
    for (; p < end; p += 32) acc += g_ew[p];
    #pragma unroll
    for (int d = 16; d; d >>= 1) acc += __shfl_down_sync(0xffffffffu, acc, d);
    if (lane == 0) {
        float di = g_dinv[w];
        g_a1[w] = acc + di * di;
    }
}

// ---------------------------------------------------------------------------
// fp32 -> fp16 convert
// ---------------------------------------------------------------------------
__global__ void k_f2h(const float* __restrict__ X, __half* __restrict__ H, int n2) {
    int i = blockIdx.x * blockDim.x + threadIdx.x;
    if (i < n2) {
        float2 v = ((const float2*)X)[i];
        ((__half2*)H)[i] = __floats2half2_rn(v.x, v.y);
    }
}

// ---------------------------------------------------------------------------
// Aggregation Y = A_norm * X with half inputs, fp32 accumulation.
// 128 cols: lane handles 4 halves. OUTH: write half, else fp32.
// ---------------------------------------------------------------------------
__device__ __forceinline__ float4 h4_to_f4(float2 raw) {
    __half2 h0 = *reinterpret_cast<__half2*>(&raw.x);
    __half2 h1 = *reinterpret_cast<__half2*>(&raw.y);
    float2 f0 = __half22float2(h0);
    float2 f1 = __half22float2(h1);
    return make_float4(f0.x, f0.y, f1.x, f1.y);
}

template <bool OUTH>
__global__ void k_aggh128(const __half* __restrict__ X, void* __restrict__ Y, int n) {
    int w = (blockIdx.x * blockDim.x + threadIdx.x) >> 5;
    int lane = threadIdx.x & 31;
    if (w >= n) return;
    const float2* Xv = (const float2*)X;   // 4 halves per float2
    float di = g_dinv[w];
    float sw = di * di;
    float4 acc = h4_to_f4(Xv[(size_t)w * 32 + lane]);
    acc.x *= sw; acc.y *= sw; acc.z *= sw; acc.w *= sw;
    int p = g_off[w], end = g_off[w + 1];
    for (; p + 4 <= end; p += 4) {
        int   s0 = g_eidx[p + 0], s1 = g_eidx[p + 1], s2 = g_eidx[p + 2], s3 = g_eidx[p + 3];
        float w0 = g_ew[p + 0],   w1 = g_ew[p + 1],   w2 = g_ew[p + 2],   w3 = g_ew[p + 3];
        float4 a = h4_to_f4(Xv[(size_t)s0 * 32 + lane]);
        float4 b = h4_to_f4(Xv[(size_t)s1 * 32 + lane]);
        float4 c = h4_to_f4(Xv[(size_t)s2 * 32 + lane]);
        float4 d = h4_to_f4(Xv[(size_t)s3 * 32 + lane]);
        acc.x += w0 * a.x + w1 * b.x + w2 * c.x + w3 * d.x;
        acc.y += w0 * a.y + w1 * b.y + w2 * c.y + w3 * d.y;
        acc.z += w0 * a.z + w1 * b.z + w2 * c.z + w3 * d.z;
        acc.w += w0 * a.w + w1 * b.w + w2 * c.w + w3 * d.w;
    }
    for (; p < end; p++) {
        int s = g_eidx[p]; float w0 = g_ew[p];
        float4 a = h4_to_f4(Xv[(size_t)s * 32 + lane]);
        acc.x += w0 * a.x; acc.y += w0 * a.y; acc.z += w0 * a.z; acc.w += w0 * a.w;
    }
    if (OUTH) {
        float2 raw;
        *reinterpret_cast<__half2*>(&raw.x) = __floats2half2_rn(acc.x, acc.y);
        *reinterpret_cast<__half2*>(&raw.y) = __floats2half2_rn(acc.z, acc.w);
        ((float2*)Y)[(size_t)w * 32 + lane] = raw;
    } else {
        ((float4*)Y)[(size_t)w * 32 + lane] = acc;
    }
}

// 64 cols: lane handles 2 halves.
template <bool OUTH>
__global__ void k_aggh64(const __half* __restrict__ X, void* __restrict__ Y, int n) {
    int w = (blockIdx.x * blockDim.x + threadIdx.x) >> 5;
    int lane = threadIdx.x & 31;
    if (w >= n) return;
    const __half2* Xv = (const __half2*)X;
    float di = g_dinv[w];
    float sw = di * di;
    float2 acc = __half22float2(Xv[(size_t)w * 32 + lane]);
    acc.x *= sw; acc.y *= sw;
    int p = g_off[w], end = g_off[w + 1];
    for (; p + 4 <= end; p += 4) {
        int   s0 = g_eidx[p + 0], s1 = g_eidx[p + 1], s2 = g_eidx[p + 2], s3 = g_eidx[p + 3];
        float w0 = g_ew[p + 0],   w1 = g_ew[p + 1],   w2 = g_ew[p + 2],   w3 = g_ew[p + 3];
        float2 a = __half22float2(Xv[(size_t)s0 * 32 + lane]);
        float2 b = __half22float2(Xv[(size_t)s1 * 32 + lane]);
        float2 c = __half22float2(Xv[(size_t)s2 * 32 + lane]);
        float2 d = __half22float2(Xv[(size_t)s3 * 32 + lane]);
        acc.x += w0 * a.x + w1 * b.x + w2 * c.x + w3 * d.x;
        acc.y += w0 * a.y + w1 * b.y + w2 * c.y + w3 * d.y;
    }
    for (; p < end; p++) {
        int s = g_eidx[p]; float w0 = g_ew[p];
        float2 a = __half22float2(Xv[(size_t)s * 32 + lane]);
        acc.x += w0 * a.x; acc.y += w0 * a.y;
    }
    if (OUTH) {
        ((__half2*)Y)[(size_t)w * 32 + lane] = __floats2half2_rn(acc.x, acc.y);
    } else {
        ((float2*)Y)[(size_t)w * 32 + lane] = acc;
    }
}

// ---------------------------------------------------------------------------
// GEMMs
// ---------------------------------------------------------------------------
__device__ __forceinline__ void fma4(float4& acc, float s, const float4& v) {
    acc.x = fmaf(s, v.x, acc.x);
    acc.y = fmaf(s, v.y, acc.y);
    acc.z = fmaf(s, v.z, acc.z);
    acc.w = fmaf(s, v.w, acc.w);
}

// Plain scalar GEMM (tiny weight-combine precomputes only)
template <int KDIM>
__global__ void k_gemm2(const float* __restrict__ X, const float* __restrict__ W,
                        const float* __restrict__ b, float* __restrict__ Y, int M) {
    extern __shared__ float sm[];
    float* sW = sm;
    float* sb = sm + KDIM * 128;
    for (int idx = threadIdx.x; idx < KDIM * 32; idx += blockDim.x)
        ((float4*)sW)[idx] = ((const float4*)W)[idx];
    if (threadIdx.x < 128) sb[threadIdx.x] = b[threadIdx.x];
    __syncthreads();

    int lane = threadIdx.x & 31;
    int wg = (blockIdx.x * blockDim.x + threadIdx.x) >> 5;
    int nw = (gridDim.x * blockDim.x) >> 5;
    for (int r0 = wg * 2; r0 < M; r0 += nw * 2) {
        int r1 = r0 + 1;
        bool has1 = (r1 < M);
        const float* x0 = X + (size_t)r0 * KDIM;
        const float* x1 = X + (size_t)(has1 ? r1 : r0) * KDIM;
        float4 acc0 = ((const float4*)sb)[lane];
        float4 acc1 = acc0;
        #pragma unroll 8
        for (int k = 0; k < KDIM; k += 4) {
            float4 a = *(const float4*)(x0 + k);
            float4 c = *(const float4*)(x1 + k);
            float4 w0 = ((const float4*)(sW + (size_t)(k + 0) * 128))[lane];
            float4 w1 = ((const float4*)(sW + (size_t)(k + 1) * 128))[lane];
            float4 w2 = ((const float4*)(sW + (size_t)(k + 2) * 128))[lane];
            float4 w3 = ((const float4*)(sW + (size_t)(k + 3) * 128))[lane];
            fma4(acc0, a.x, w0); fma4(acc1, c.x, w0);
            fma4(acc0, a.y, w1); fma4(acc1, c.y, w1);
            fma4(acc0, a.z, w2); fma4(acc1, c.z, w2);
            fma4(acc0, a.w, w3); fma4(acc1, c.w, w3);
        }
        *(float4*)(Y + (size_t)r0 * 128 + lane * 4) = acc0;
        if (has1) *(float4*)(Y + (size_t)r1 * 128 + lane * 4) = acc1;
    }
}

// Production GEMM, f32x2 packed FMA: Y = X @ W + b + a1 (x) v
template <int KDIM>
__global__ void k_gemm_r1(const float* __restrict__ X, const float* __restrict__ W,
                          const float* __restrict__ b, const float* __restrict__ v,
                          float* __restrict__ Y, int M) {
    extern __shared__ float sm[];
    float* sW = sm;                 // KDIM * 128
    float* sb = sm + KDIM * 128;    // 128
    float* sv = sb + 128;           // 128
    for (int idx = threadIdx.x; idx < KDIM * 32; idx += blockDim.x)
        ((float4*)sW)[idx] = ((const float4*)W)[idx];
    if (threadIdx.x < 128) {
        sb[threadIdx.x] = b[threadIdx.x];
        sv[threadIdx.x] = v[threadIdx.x];
    }
    __syncthreads();

    const ulonglong2* sW2 = (const ulonglong2*)sW;
    int lane = threadIdx.x & 31;
    int wg = (blockIdx.x * blockDim.x + threadIdx.x) >> 5;
    int nw = (gridDim.x * blockDim.x) >> 5;
    for (int r0 = wg * 2; r0 < M; r0 += nw * 2) {
        int r1 = r0 + 1;
        bool has1 = (r1 < M);
        const float* x0 = X + (size_t)r0 * KDIM;
        const float* x1 = X + (size_t)(has1 ? r1 : r0) * KDIM;
        float4 bb = ((const float4*)sb)[lane];
        float4 vv = ((const float4*)sv)[lane];
        float a0 = g_a1[r0];
        float a1v = g_a1[has1 ? r1 : r0];
        u64 acc0l = pack2(fmaf(a0, vv.x, bb.x),  fmaf(a0, vv.y, bb.y));
        u64 acc0h = pack2(fmaf(a0, vv.z, bb.z),  fmaf(a0, vv.w, bb.w));
        u64 acc1l = pack2(fmaf(a1v, vv.x, bb.x), fmaf(a1v, vv.y, bb.y));
        u64 acc1h = pack2(fmaf(a1v, vv.z, bb.z), fmaf(a1v, vv.w, bb.w));
        #pragma unroll 8
        for (int k = 0; k < KDIM; k += 4) {
            float4 a = *(const float4*)(x0 + k);
            float4 c = *(const float4*)(x1 + k);
            ulonglong2 w0 = sW2[(size_t)(k + 0) * 32 + lane];
            ulonglong2 w1 = sW2[(size_t)(k + 1) * 32 + lane];
            ulonglong2 w2 = sW2[(size_t)(k + 2) * 32 + lane];
            ulonglong2 w3 = sW2[(size_t)(k + 3) * 32 + lane];
            u64 s;
            s = bcast2(a.x); fmaa2(acc0l, s, w0.x); fmaa2(acc0h, s, w0.y);
            s = bcast2(c.x); fmaa2(acc1l, s, w0.x); fmaa2(acc1h, s, w0.y);
            s = bcast2(a.y); fmaa2(acc0l, s, w1.x); fmaa2(acc0h, s, w1.y);
            s = bcast2(c.y); fmaa2(acc1l, s, w1.x); fmaa2(acc1h, s, w1.y);
            s = bcast2(a.z); fmaa2(acc0l, s, w2.x); fmaa2(acc0h, s, w2.y);
            s = bcast2(c.z); fmaa2(acc1l, s, w2.x); fmaa2(acc1h, s, w2.y);
            s = bcast2(a.w); fmaa2(acc0l, s, w3.x); fmaa2(acc0h, s, w3.y);
            s = bcast2(c.w); fmaa2(acc1l, s, w3.x); fmaa2(acc1h, s, w3.y);
        }
        float2 o0 = unpack2(acc0l), o1 = unpack2(acc0h);
        *(float4*)(Y + (size_t)r0 * 128 + lane * 4) = make_float4(o0.x, o0.y, o1.x, o1.y);
        if (has1) {
            float2 p0 = unpack2(acc1l), p1 = unpack2(acc1h);
            *(float4*)(Y + (size_t)r1 * 128 + lane * 4) = make_float4(p0.x, p0.y, p1.x, p1.y);
        }
    }
}

// Pack [W_mean | W_lv] into 128x128, same for bias.
__global__ void k_pack(const float* __restrict__ Wm, const float* __restrict__ Wl,
                       const float* __restrict__ bm, const float* __restrict__ bl) {
    int idx = blockIdx.x * blockDim.x + threadIdx.x;
    if (idx < 128 * 128) {
        int k = idx >> 7, c = idx & 127;
        g_Wc[idx] = (c < 64) ? Wm[k * 64 + c] : Wl[k * 64 + (c - 64)];
    }
    if (idx < 128) g_bc[idx] = (idx < 64) ? bm[idx] : bl[idx - 64];
}

// z = noise*exp(0.5*lv) + mean; split packed [mean|lv]; also emit half z.
__global__ void k_mlz(const float* __restrict__ ML, const float* __restrict__ noise,
                      float* __restrict__ z, float* __restrict__ m,
                      float* __restrict__ lv, __half* __restrict__ zh, int N) {
    int i = blockIdx.x * blockDim.x + threadIdx.x;  // over N*16 float4 groups
    if (i >= N * 16) return;
    int row = i >> 4, c4 = i & 15;
    float4 me  = *(const float4*)(ML + (size_t)row * 128 + c4 * 4);
    float4 lvv = *(const float4*)(ML + (size_t)row * 128 + 64 + c4 * 4);
    float4 nz  = ((const float4*)noise)[i];
    float4 zz;
    zz.x = fmaf(nz.x, expf(0.5f * lvv.x), me.x);
    zz.y = fmaf(nz.y, expf(0.5f * lvv.y), me.y);
    zz.z = fmaf(nz.z, expf(0.5f * lvv.z), me.z);
    zz.w = fmaf(nz.w, expf(0.5f * lvv.w), me.w);
    ((float4*)z)[i] = zz;
    ((float4*)m)[i] = me;
    ((float4*)lv)[i] = lvv;
    float2 raw;
    *reinterpret_cast<__half2*>(&raw.x) = __floats2half2_rn(zz.x, zz.y);
    *reinterpret_cast<__half2*>(&raw.y) = __floats2half2_rn(zz.z, zz.w);
    ((float2*)zh)[i] = raw;
}

// ---------------------------------------------------------------------------
extern "C" void kernel_launch(void* const* d_in, const int* in_sizes, int n_in,
                              void* d_out, int out_size) {
    const float* feature = (const float*)d_in[0];
    const int*   ei      = (const int*)d_in[1];
    const float* noise   = (const float*)d_in[2];
    const float* W_enc   = (const float*)d_in[3];
    const float* b_enc   = (const float*)d_in[4];
    const float* W_mean  = (const float*)d_in[5];
    const float* b_mean  = (const float*)d_in[6];
    const float* W_lv    = (const float*)d_in[7];
    const float* b_lv    = (const float*)d_in[8];
    const float* W_d1    = (const float*)d_in[9];
    const float* b_d1    = (const float*)d_in[10];
    const float* W_d2    = (const float*)d_in[11];
    const float* b_d2    = (const float*)d_in[12];

    int N = in_sizes[0] / 128;
    int E = in_sizes[1] / 2;
    const int* src = ei;
    const int* dst = ei + E;

    float* zout  = (float*)d_out;
    float* mout  = zout + (size_t)N * 64;
    float* lvout = mout + (size_t)N * 64;
    float* oout  = lvout + (size_t)N * 64;

    float *bufA, *bufB, *Wc, *bc, *Wem, *bem, *Wdd, *bdd, *zerov;
    __half *hA, *hB;
    cudaGetSymbolAddress((void**)&bufA, g_bufA);
    cudaGetSymbolAddress((void**)&bufB, g_bufB);
    cudaGetSymbolAddress((void**)&hA, g_hA);
    cudaGetSymbolAddress((void**)&hB, g_hB);
    cudaGetSymbolAddress((void**)&Wc, g_Wc);
    cudaGetSymbolAddress((void**)&bc, g_bc);
    cudaGetSymbolAddress((void**)&Wem, g_Wem);
    cudaGetSymbolAddress((void**)&bem, g_bem);
    cudaGetSymbolAddress((void**)&Wdd, g_Wdd);
    cudaGetSymbolAddress((void**)&bdd, g_bdd);
    cudaGetSymbolAddress((void**)&zerov, g_zero);

    const int smem128  = 128 * 128 * 4 + 512;
    const int smem128r = 128 * 128 * 4 + 1024;
    const int smem64r  = 64 * 128 * 4 + 1024;
    cudaFuncSetAttribute(k_gemm2<128>,   cudaFuncAttributeMaxDynamicSharedMemorySize, smem128);
    cudaFuncSetAttribute(k_gemm_r1<128>, cudaFuncAttributeMaxDynamicSharedMemorySize, smem128r);
    cudaFuncSetAttribute(k_gemm_r1<64>,  cudaFuncAttributeMaxDynamicSharedMemorySize, smem64r);

    int tb = 256;
    int nBlkN = (N + tb - 1) / tb;
    int nBlkE = (E + tb - 1) / tb;
    int nBlkW = (N * 32 + tb - 1) / tb;   // warp per node
    int nSBlks = (N + SCAN_BLK - 1) / SCAN_BLK;
    int gemmBlocks = 444;

    // --- CSR build ---
    k_zero_cnt<<<nBlkN, tb>>>(N);
    k_count<<<nBlkE, tb>>>(dst, E);
    k_dinv<<<nBlkN, tb>>>(N);
    k_scan_local<<<nSBlks, 256>>>(N);
    k_scan_bsums<<<1, 64>>>(nSBlks, N);
    k_scan_add<<<nBlkN, tb>>>(N);
    k_fill<<<nBlkE, tb>>>(src, dst, E);
    k_a1<<<nBlkW, tb>>>(N);

    // --- weight precomputes (tiny) ---
    k_pack<<<(128 * 128 + tb - 1) / tb, tb>>>(W_mean, W_lv, b_mean, b_lv);
    k_gemm2<128><<<8, tb, smem128>>>(W_enc, Wc, zerov, Wem, 128);   // We @ Wc
    k_gemm2<128><<<1, tb, smem128>>>(b_enc, Wc, zerov, bem, 1);     // be @ Wc
    k_gemm2<128><<<4, tb, smem128>>>(W_d1, W_d2, zerov, Wdd, 64);   // Wd1 @ Wd2
    k_gemm2<128><<<1, tb, smem128>>>(b_d1, W_d2, zerov, bdd, 1);    // bd1 @ Wd2

    // --- encoder collapsed: [mean|lv] = (A A f) Wem + a1 (x) bem + bc ---
    k_f2h<<<(N * 64 + tb - 1) / tb, tb>>>(feature, hA, N * 64);
    k_aggh128<true><<<nBlkW, tb>>>(hA, hB, N);
    k_aggh128<false><<<nBlkW, tb>>>(hB, bufA, N);
    k_gemm_r1<128><<<gemmBlocks, tb, smem128r>>>(bufA, Wem, bc, bem, bufB, N);
    k_mlz<<<(N * 16 + tb - 1) / tb, tb>>>(bufB, noise, zout, mout, lvout, hA, N);

    // --- decoder collapsed: out = (A A z) Wdd + a1 (x) bdd + bd2 ---
    k_aggh64<true><<<nBlkW, tb>>>(hA, hB, N);
    k_aggh64<false><<<nBlkW, tb>>>(hB, bufA, N);
    k_gemm_r1<64><<<gemmBlocks, tb, smem64r>>>(bufA, Wdd, b_d2, bdd, oout, N);
}

// round 7
// speedup vs baseline: 1.1545x; 1.1522x over previous
#include <cuda_runtime.h>
#include <cuda_fp16.h>
#include <math.h>

// Problem-shape scratch (allocation-free rule: __device__ globals).
#define NMAX 50048
#define EMAX 1700000
#define SCAN_BLK 1024
#define MAX_SBLKS ((NMAX + SCAN_BLK - 1) / SCAN_BLK)

__device__ int    g_cnt[NMAX];
__device__ int    g_off[NMAX + 1];
__device__ int    g_cursor[NMAX];
__device__ int    g_bsum[MAX_SBLKS + 1];
__device__ float  g_dinv[NMAX];
__device__ float  g_a1[NMAX];        // A_norm * ones
__device__ int    g_eidx[EMAX];
__device__ float  g_ew[EMAX];
__device__ float  g_bufA[6500000];   // N x 128 fp32 scratch
__device__ float  g_bufB[6500000];   // N x 128 fp32 scratch
__device__ __half g_hA[6500000];     // N x 128 half scratch
__device__ __half g_hB[6500000];     // N x 128 half scratch
__device__ float  g_Wc[128 * 128];   // packed [W_mean | W_lv]
__device__ float  g_bc[128];         // packed [b_mean | b_lv]
__device__ float  g_Wem[128 * 128];  // W_enc @ Wc
__device__ float  g_bem[128];        // b_enc @ Wc
__device__ float  g_Wdd[64 * 128];   // W_d1 @ W_d2
__device__ float  g_bdd[128];        // b_d1 @ W_d2
__device__ float  g_zero[128];       // stays zero

// ---------------------------------------------------------------------------
// f32x2 packed-FMA helpers (FFMA2 — only reachable via PTX fma.rn.f32x2)
// ---------------------------------------------------------------------------
typedef unsigned long long u64;
__device__ __forceinline__ u64 bcast2(float s) {
    u64 r; asm("mov.b64 %0, {%1, %1};" : "=l"(r) : "f"(s)); return r;
}
__device__ __forceinline__ u64 pack2(float lo, float hi) {
    u64 r; asm("mov.b64 %0, {%1, %2};" : "=l"(r) : "f"(lo), "f"(hi)); return r;
}
__device__ __forceinline__ float2 unpack2(u64 v) {
    float2 f; asm("mov.b64 {%0, %1}, %2;" : "=f"(f.x), "=f"(f.y) : "l"(v)); return f;
}
__device__ __forceinline__ void fmaa2(u64& acc, u64 a, u64 b) {
    asm("fma.rn.f32x2 %0, %1, %2, %0;" : "+l"(acc) : "l"(a), "l"(b));
}

// ---------------------------------------------------------------------------
// CSR build
// ---------------------------------------------------------------------------
__global__ void k_count(const int* __restrict__ dst, int E) {
    int i = blockIdx.x * blockDim.x + threadIdx.x;
    if (i < E) atomicAdd(&g_cnt[dst[i]], 1);
}

__global__ void k_dinv(int n) {
    int i = blockIdx.x * blockDim.x + threadIdx.x;
    if (i < n) g_dinv[i] = rsqrtf((float)g_cnt[i] + 1.0f);
}

__global__ void k_scan_local(int n) {
    int b = blockIdx.x;
    int t = threadIdx.x;          // 256 threads
    int lane = t & 31, wid = t >> 5;
    int idx = b * SCAN_BLK + t * 4;
    int v0 = (idx + 0 < n) ? g_cnt[idx + 0] : 0;
    int v1 = (idx + 1 < n) ? g_cnt[idx + 1] : 0;
    int v2 = (idx + 2 < n) ? g_cnt[idx + 2] : 0;
    int v3 = (idx + 3 < n) ? g_cnt[idx + 3] : 0;
    int s = v0 + v1 + v2 + v3;
    int pre = s;
    #pragma unroll
    for (int d = 1; d < 32; d <<= 1) {
        int t2 = __shfl_up_sync(0xffffffffu, pre, d);
        if (lane >= d) pre += t2;
    }
    __shared__ int wsum[8];
    __shared__ int wexcl[8];
    if (lane == 31) wsum[wid] = pre;
    __syncthreads();
    if (t == 0) {
        int acc = 0;
        #pragma unroll
        for (int i = 0; i < 8; i++) { wexcl[i] = acc; acc += wsum[i]; }
        g_bsum[b] = acc;
    }
    __syncthreads();
    int run = (pre - s) + wexcl[wid];
    if (idx + 0 < n) g_off[idx + 0] = run;  run += v0;
    if (idx + 1 < n) g_off[idx + 1] = run;  run += v1;
    if (idx + 2 < n) g_off[idx + 2] = run;  run += v2;
    if (idx + 3 < n) g_off[idx + 3] = run;
}

__global__ void k_scan_bsums(int nb, int n) {
    __shared__ int sh[64];
    int t = threadIdx.x;           // 64 threads, nb <= 49
    int v = (t < nb) ? g_bsum[t] : 0;
    sh[t] = v;
    __syncthreads();
    #pragma unroll
    for (int ofs = 1; ofs < 64; ofs <<= 1) {
        int x = (t >= ofs) ? sh[t - ofs] : 0;
        __syncthreads();
        sh[t] += x;
        __syncthreads();
    }
    if (t < nb) g_bsum[t] = sh[t] - v;
    if (t == 63) g_off[n] = sh[63];
}

__global__ void k_scan_add(int n) {
    int i = blockIdx.x * blockDim.x + threadIdx.x;
    if (i < n) {
        int o = g_off[i] + g_bsum[i >> 10];
        g_off[i] = o;
        g_cursor[i] = o;
    }
}

__global__ void k_fill(const int* __restrict__ src, const int* __restrict__ dst, int E) {
    int e = blockIdx.x * blockDim.x + threadIdx.x;
    if (e < E) {
        int s = src[e], d = dst[e];
        int p = atomicAdd(&g_cursor[d], 1);
        g_eidx[p] = s;
        g_ew[p] = g_dinv[s] * g_dinv[d];
    }
}

__global__ void k_a1(int n) {
    int w = (blockIdx.x * blockDim.x + threadIdx.x) >> 5;
    int lane = threadIdx.x & 31;
    if (w >= n) return;
    float acc = 0.0f;
    int p = g_off[w] + lane, end = g_off[w + 1];
    for (; p < end; p += 32) acc += g_ew[p];
    #pragma unroll
    for (int d = 16; d; d >>= 1) acc += __shfl_down_sync(0xffffffffu, acc, d);
    if (lane == 0) {
        float di = g_dinv[w];
        g_a1[w] = acc + di * di;
    }
}

// ---------------------------------------------------------------------------
// fp32 -> fp16 convert
// ---------------------------------------------------------------------------
__global__ void k_f2h(const float* __restrict__ X, __half* __restrict__ H, int n2) {
    int i = blockIdx.x * blockDim.x + threadIdx.x;
    if (i < n2) {
        float2 v = ((const float2*)X)[i];
        ((__half2*)H)[i] = __floats2half2_rn(v.x, v.y);
    }
}

// ---------------------------------------------------------------------------
// Aggregation Y = A_norm * X, half inputs, fp32 accumulation.
// Unroll-8 with vectorized metadata loads (peel to 4-alignment).
// ---------------------------------------------------------------------------
__device__ __forceinline__ float4 h4_to_f4(float2 raw) {
    __half2 h0 = *reinterpret_cast<__half2*>(&raw.x);
    __half2 h1 = *reinterpret_cast<__half2*>(&raw.y);
    float2 f0 = __half22float2(h0);
    float2 f1 = __half22float2(h1);
    return make_float4(f0.x, f0.y, f1.x, f1.y);
}
__device__ __forceinline__ void acc4(float4& acc, float w, float4 a) {
    acc.x = fmaf(w, a.x, acc.x);
    acc.y = fmaf(w, a.y, acc.y);
    acc.z = fmaf(w, a.z, acc.z);
    acc.w = fmaf(w, a.w, acc.w);
}

template <bool OUTH>
__global__ void k_aggh128(const __half* __restrict__ X, void* __restrict__ Y, int n) {
    int w = (blockIdx.x * blockDim.x + threadIdx.x) >> 5;
    int lane = threadIdx.x & 31;
    if (w >= n) return;
    const float2* Xv = (const float2*)X;   // 4 halves per float2
    float di = g_dinv[w];
    float sw = di * di;
    float4 acc = h4_to_f4(Xv[(size_t)w * 32 + lane]);
    acc.x *= sw; acc.y *= sw; acc.z *= sw; acc.w *= sw;
    int p = g_off[w], end = g_off[w + 1];
    // peel to 4-alignment for vector metadata loads
    while (p < end && (p & 3)) {
        float wt = g_ew[p];
        acc4(acc, wt, h4_to_f4(Xv[(size_t)g_eidx[p] * 32 + lane]));
        p++;
    }
    for (; p + 8 <= end; p += 8) {
        int4   ia = *(const int4*)(g_eidx + p);
        int4   ib = *(const int4*)(g_eidx + p + 4);
        float4 wa = *(const float4*)(g_ew + p);
        float4 wb = *(const float4*)(g_ew + p + 4);
        float2 r0 = Xv[(size_t)ia.x * 32 + lane];
        float2 r1 = Xv[(size_t)ia.y * 32 + lane];
        float2 r2 = Xv[(size_t)ia.z * 32 + lane];
        float2 r3 = Xv[(size_t)ia.w * 32 + lane];
        float2 r4 = Xv[(size_t)ib.x * 32 + lane];
        float2 r5 = Xv[(size_t)ib.y * 32 + lane];
        float2 r6 = Xv[(size_t)ib.z * 32 + lane];
        float2 r7 = Xv[(size_t)ib.w * 32 + lane];
        acc4(acc, wa.x, h4_to_f4(r0));
        acc4(acc, wa.y, h4_to_f4(r1));
        acc4(acc, wa.z, h4_to_f4(r2));
        acc4(acc, wa.w, h4_to_f4(r3));
        acc4(acc, wb.x, h4_to_f4(r4));
        acc4(acc, wb.y, h4_to_f4(r5));
        acc4(acc, wb.z, h4_to_f4(r6));
        acc4(acc, wb.w, h4_to_f4(r7));
    }
    for (; p < end; p++) {
        float wt = g_ew[p];
        acc4(acc, wt, h4_to_f4(Xv[(size_t)g_eidx[p] * 32 + lane]));
    }
    if (OUTH) {
        float2 raw;
        *reinterpret_cast<__half2*>(&raw.x) = __floats2half2_rn(acc.x, acc.y);
        *reinterpret_cast<__half2*>(&raw.y) = __floats2half2_rn(acc.z, acc.w);
        ((float2*)Y)[(size_t)w * 32 + lane] = raw;
    } else {
        ((float4*)Y)[(size_t)w * 32 + lane] = acc;
    }
}

template <bool OUTH>
__global__ void k_aggh64(const __half* __restrict__ X, void* __restrict__ Y, int n) {
    int w = (blockIdx.x * blockDim.x + threadIdx.x) >> 5;
    int lane = threadIdx.x & 31;
    if (w >= n) return;
    const __half2* Xv = (const __half2*)X;
    float di = g_dinv[w];
    float sw = di * di;
    float2 acc = __half22float2(Xv[(size_t)w * 32 + lane]);
    acc.x *= sw; acc.y *= sw;
    int p = g_off[w], end = g_off[w + 1];
    while (p < end && (p & 3)) {
        float wt = g_ew[p];
        float2 a = __half22float2(Xv[(size_t)g_eidx[p] * 32 + lane]);
        acc.x = fmaf(wt, a.x, acc.x); acc.y = fmaf(wt, a.y, acc.y);
        p++;
    }
    for (; p + 8 <= end; p += 8) {
        int4   ia = *(const int4*)(g_eidx + p);
        int4   ib = *(const int4*)(g_eidx + p + 4);
        float4 wa = *(const float4*)(g_ew + p);
        float4 wb = *(const float4*)(g_ew + p + 4);
        __half2 r0 = Xv[(size_t)ia.x * 32 + lane];
        __half2 r1 = Xv[(size_t)ia.y * 32 + lane];
        __half2 r2 = Xv[(size_t)ia.z * 32 + lane];
        __half2 r3 = Xv[(size_t)ia.w * 32 + lane];
        __half2 r4 = Xv[(size_t)ib.x * 32 + lane];
        __half2 r5 = Xv[(size_t)ib.y * 32 + lane];
        __half2 r6 = Xv[(size_t)ib.z * 32 + lane];
        __half2 r7 = Xv[(size_t)ib.w * 32 + lane];
        float2 f;
        f = __half22float2(r0); acc.x = fmaf(wa.x, f.x, acc.x); acc.y = fmaf(wa.x, f.y, acc.y);
        f = __half22float2(r1); acc.x = fmaf(wa.y, f.x, acc.x); acc.y = fmaf(wa.y, f.y, acc.y);
        f = __half22float2(r2); acc.x = fmaf(wa.z, f.x, acc.x); acc.y = fmaf(wa.z, f.y, acc.y);
        f = __half22float2(r3); acc.x = fmaf(wa.w, f.x, acc.x); acc.y = fmaf(wa.w, f.y, acc.y);
        f = __half22float2(r4); acc.x = fmaf(wb.x, f.x, acc.x); acc.y = fmaf(wb.x, f.y, acc.y);
        f = __half22float2(r5); acc.x = fmaf(wb.y, f.x, acc.x); acc.y = fmaf(wb.y, f.y, acc.y);
        f = __half22float2(r6); acc.x = fmaf(wb.z, f.x, acc.x); acc.y = fmaf(wb.z, f.y, acc.y);
        f = __half22float2(r7); acc.x = fmaf(wb.w, f.x, acc.x); acc.y = fmaf(wb.w, f.y, acc.y);
    }
    for (; p < end; p++) {
        float wt = g_ew[p];
        float2 a = __half22float2(Xv[(size_t)g_eidx[p] * 32 + lane]);
        acc.x = fmaf(wt, a.x, acc.x); acc.y = fmaf(wt, a.y, acc.y);
    }
    if (OUTH) {
        ((__half2*)Y)[(size_t)w * 32 + lane] = __floats2half2_rn(acc.x, acc.y);
    } else {
        ((float2*)Y)[(size_t)w * 32 + lane] = acc;
    }
}

// ---------------------------------------------------------------------------
// GEMMs
// ---------------------------------------------------------------------------
__device__ __forceinline__ void fma4(float4& acc, float s, const float4& v) {
    acc.x = fmaf(s, v.x, acc.x);
    acc.y = fmaf(s, v.y, acc.y);
    acc.z = fmaf(s, v.z, acc.z);
    acc.w = fmaf(s, v.w, acc.w);
}

// Plain scalar GEMM (tiny weight-combine precomputes only)
template <int KDIM>
__global__ void k_gemm2(const float* __restrict__ X, const float* __restrict__ W,
                        const float* __restrict__ b, float* __restrict__ Y, int M) {
    extern __shared__ float sm[];
    float* sW = sm;
    float* sb = sm + KDIM * 128;
    for (int idx = threadIdx.x; idx < KDIM * 32; idx += blockDim.x)
        ((float4*)sW)[idx] = ((const float4*)W)[idx];
    if (threadIdx.x < 128) sb[threadIdx.x] = b[threadIdx.x];
    __syncthreads();

    int lane = threadIdx.x & 31;
    int wg = (blockIdx.x * blockDim.x + threadIdx.x) >> 5;
    int nw = (gridDim.x * blockDim.x) >> 5;
    for (int r0 = wg * 2; r0 < M; r0 += nw * 2) {
        int r1 = r0 + 1;
        bool has1 = (r1 < M);
        const float* x0 = X + (size_t)r0 * KDIM;
        const float* x1 = X + (size_t)(has1 ? r1 : r0) * KDIM;
        float4 acc0 = ((const float4*)sb)[lane];
        float4 acc1 = acc0;
        #pragma unroll 8
        for (int k = 0; k < KDIM; k += 4) {
            float4 a = *(const float4*)(x0 + k);
            float4 c = *(const float4*)(x1 + k);
            float4 w0 = ((const float4*)(sW + (size_t)(k + 0) * 128))[lane];
            float4 w1 = ((const float4*)(sW + (size_t)(k + 1) * 128))[lane];
            float4 w2 = ((const float4*)(sW + (size_t)(k + 2) * 128))[lane];
            float4 w3 = ((const float4*)(sW + (size_t)(k + 3) * 128))[lane];
            fma4(acc0, a.x, w0); fma4(acc1, c.x, w0);
            fma4(acc0, a.y, w1); fma4(acc1, c.y, w1);
            fma4(acc0, a.z, w2); fma4(acc1, c.z, w2);
            fma4(acc0, a.w, w3); fma4(acc1, c.w, w3);
        }
        *(float4*)(Y + (size_t)r0 * 128 + lane * 4) = acc0;
        if (has1) *(float4*)(Y + (size_t)r1 * 128 + lane * 4) = acc1;
    }
}

// Production GEMM, 4 rows/warp, f32x2 packed FMA: Y = X @ W + b + a1 (x) v
template <int KDIM>
__global__ void k_gemm_r1(const float* __restrict__ X, const float* __restrict__ W,
                          const float* __restrict__ b, const float* __restrict__ v,
                          float* __restrict__ Y, int M) {
    extern __shared__ float sm[];
    float* sW = sm;                 // KDIM * 128
    float* sb = sm + KDIM * 128;    // 128
    float* sv = sb + 128;           // 128
    for (int idx = threadIdx.x; idx < KDIM * 32; idx += blockDim.x)
        ((float4*)sW)[idx] = ((const float4*)W)[idx];
    if (threadIdx.x < 128) {
        sb[threadIdx.x] = b[threadIdx.x];
        sv[threadIdx.x] = v[threadIdx.x];
    }
    __syncthreads();

    const ulonglong2* sW2 = (const ulonglong2*)sW;
    int lane = threadIdx.x & 31;
    int wg = (blockIdx.x * blockDim.x + threadIdx.x) >> 5;
    int nw = (gridDim.x * blockDim.x) >> 5;
    for (int r0 = wg * 4; r0 < M; r0 += nw * 4) {
        int rr[4];
        rr[0] = r0;
        rr[1] = (r0 + 1 < M) ? r0 + 1 : r0;
        rr[2] = (r0 + 2 < M) ? r0 + 2 : r0;
        rr[3] = (r0 + 3 < M) ? r0 + 3 : r0;
        const float* xp[4];
        u64 accl[4], acch[4];
        float4 bb = ((const float4*)sb)[lane];
        float4 vv = ((const float4*)sv)[lane];
        #pragma unroll
        for (int i = 0; i < 4; i++) {
            xp[i] = X + (size_t)rr[i] * KDIM;
            float av = g_a1[rr[i]];
            accl[i] = pack2(fmaf(av, vv.x, bb.x), fmaf(av, vv.y, bb.y));
            acch[i] = pack2(fmaf(av, vv.z, bb.z), fmaf(av, vv.w, bb.w));
        }
        #pragma unroll 4
        for (int k = 0; k < KDIM; k += 4) {
            ulonglong2 w0 = sW2[(size_t)(k + 0) * 32 + lane];
            ulonglong2 w1 = sW2[(size_t)(k + 1) * 32 + lane];
            ulonglong2 w2 = sW2[(size_t)(k + 2) * 32 + lane];
            ulonglong2 w3 = sW2[(size_t)(k + 3) * 32 + lane];
            #pragma unroll
            for (int i = 0; i < 4; i++) {
                float4 a = *(const float4*)(xp[i] + k);
                u64 s;
                s = bcast2(a.x); fmaa2(accl[i], s, w0.x); fmaa2(acch[i], s, w0.y);
                s = bcast2(a.y); fmaa2(accl[i], s, w1.x); fmaa2(acch[i], s, w1.y);
                s = bcast2(a.z); fmaa2(accl[i], s, w2.x); fmaa2(acch[i], s, w2.y);
                s = bcast2(a.w); fmaa2(accl[i], s, w3.x); fmaa2(acch[i], s, w3.y);
            }
        }
        #pragma unroll
        for (int i = 0; i < 4; i++) {
            if (r0 + i < M) {
                float2 o0 = unpack2(accl[i]), o1 = unpack2(acch[i]);
                *(float4*)(Y + (size_t)(r0 + i) * 128 + lane * 4) =
                    make_float4(o0.x, o0.y, o1.x, o1.y);
            }
        }
    }
}

// Pack [W_mean | W_lv] into 128x128, same for bias.
__global__ void k_pack(const float* __restrict__ Wm, const float* __restrict__ Wl,
                       const float* __restrict__ bm, const float* __restrict__ bl) {
    int idx = blockIdx.x * blockDim.x + threadIdx.x;
    if (idx < 128 * 128) {
        int k = idx >> 7, c = idx & 127;
        g_Wc[idx] = (c < 64) ? Wm[k * 64 + c] : Wl[k * 64 + (c - 64)];
    }
    if (idx < 128) g_bc[idx] = (idx < 64) ? bm[idx] : bl[idx - 64];
}

// z = noise*exp(0.5*lv) + mean; split packed [mean|lv]; also emit half z.
__global__ void k_mlz(const float* __restrict__ ML, const float* __restrict__ noise,
                      float* __restrict__ z, float* __restrict__ m,
                      float* __restrict__ lv, __half* __restrict__ zh, int N) {
    int i = blockIdx.x * blockDim.x + threadIdx.x;  // over N*16 float4 groups
    if (i >= N * 16) return;
    int row = i >> 4, c4 = i & 15;
    float4 me  = *(const float4*)(ML + (size_t)row * 128 + c4 * 4);
    float4 lvv = *(const float4*)(ML + (size_t)row * 128 + 64 + c4 * 4);
    float4 nz  = ((const float4*)noise)[i];
    float4 zz;
    zz.x = fmaf(nz.x, expf(0.5f * lvv.x), me.x);
    zz.y = fmaf(nz.y, expf(0.5f * lvv.y), me.y);
    zz.z = fmaf(nz.z, expf(0.5f * lvv.z), me.z);
    zz.w = fmaf(nz.w, expf(0.5f * lvv.w), me.w);
    ((float4*)z)[i] = zz;
    ((float4*)m)[i] = me;
    ((float4*)lv)[i] = lvv;
    float2 raw;
    *reinterpret_cast<__half2*>(&raw.x) = __floats2half2_rn(zz.x, zz.y);
    *reinterpret_cast<__half2*>(&raw.y) = __floats2half2_rn(zz.z, zz.w);
    ((float2*)zh)[i] = raw;
}

// ---------------------------------------------------------------------------
extern "C" void kernel_launch(void* const* d_in, const int* in_sizes, int n_in,
                              void* d_out, int out_size) {
    const float* feature = (const float*)d_in[0];
    const int*   ei      = (const int*)d_in[1];
    const float* noise   = (const float*)d_in[2];
    const float* W_enc   = (const float*)d_in[3];
    const float* b_enc   = (const float*)d_in[4];
    const float* W_mean  = (const float*)d_in[5];
    const float* b_mean  = (const float*)d_in[6];
    const float* W_lv    = (const float*)d_in[7];
    const float* b_lv    = (const float*)d_in[8];
    const float* W_d1    = (const float*)d_in[9];
    const float* b_d1    = (const float*)d_in[10];
    const float* W_d2    = (const float*)d_in[11];
    const float* b_d2    = (const float*)d_in[12];

    int N = in_sizes[0] / 128;
    int E = in_sizes[1] / 2;
    const int* src = ei;
    const int* dst = ei + E;

    float* zout  = (float*)d_out;
    float* mout  = zout + (size_t)N * 64;
    float* lvout = mout + (size_t)N * 64;
    float* oout  = lvout + (size_t)N * 64;

    float *bufA, *bufB, *Wc, *bc, *Wem, *bem, *Wdd, *bdd, *zerov, *cntp;
    __half *hA, *hB;
    cudaGetSymbolAddress((void**)&cntp, g_cnt);
    cudaGetSymbolAddress((void**)&bufA, g_bufA);
    cudaGetSymbolAddress((void**)&bufB, g_bufB);
    cudaGetSymbolAddress((void**)&hA, g_hA);
    cudaGetSymbolAddress((void**)&hB, g_hB);
    cudaGetSymbolAddress((void**)&Wc, g_Wc);
    cudaGetSymbolAddress((void**)&bc, g_bc);
    cudaGetSymbolAddress((void**)&Wem, g_Wem);
    cudaGetSymbolAddress((void**)&bem, g_bem);
    cudaGetSymbolAddress((void**)&Wdd, g_Wdd);
    cudaGetSymbolAddress((void**)&bdd, g_bdd);
    cudaGetSymbolAddress((void**)&zerov, g_zero);

    const int smem128  = 128 * 128 * 4 + 512;
    const int smem128r = 128 * 128 * 4 + 1024;
    const int smem64r  = 64 * 128 * 4 + 1024;
    cudaFuncSetAttribute(k_gemm2<128>,   cudaFuncAttributeMaxDynamicSharedMemorySize, smem128);
    cudaFuncSetAttribute(k_gemm_r1<128>, cudaFuncAttributeMaxDynamicSharedMemorySize, smem128r);
    cudaFuncSetAttribute(k_gemm_r1<64>,  cudaFuncAttributeMaxDynamicSharedMemorySize, smem64r);

    int tb = 256;
    int nBlkN = (N + tb - 1) / tb;
    int nBlkE = (E + tb - 1) / tb;
    int nBlkW = (N * 32 + tb - 1) / tb;   // warp per node
    int nSBlks = (N + SCAN_BLK - 1) / SCAN_BLK;
    int gemmBlocks = 444;

    // --- CSR build ---
    cudaMemsetAsync(cntp, 0, (size_t)N * sizeof(int));
    k_count<<<nBlkE, tb>>>(dst, E);
    k_dinv<<<nBlkN, tb>>>(N);
    k_scan_local<<<nSBlks, 256>>>(N);
    k_scan_bsums<<<1, 64>>>(nSBlks, N);
    k_scan_add<<<nBlkN, tb>>>(N);
    k_fill<<<nBlkE, tb>>>(src, dst, E);
    k_a1<<<nBlkW, tb>>>(N);

    // --- weight precomputes (tiny) ---
    k_pack<<<(128 * 128 + tb - 1) / tb, tb>>>(W_mean, W_lv, b_mean, b_lv);
    k_gemm2<128><<<8, tb, smem128>>>(W_enc, Wc, zerov, Wem, 128);   // We @ Wc
    k_gemm2<128><<<1, tb, smem128>>>(b_enc, Wc, zerov, bem, 1);     // be @ Wc
    k_gemm2<128><<<4, tb, smem128>>>(W_d1, W_d2, zerov, Wdd, 64);   // Wd1 @ Wd2
    k_gemm2<128><<<1, tb, smem128>>>(b_d1, W_d2, zerov, bdd, 1);    // bd1 @ Wd2

    // --- encoder collapsed: [mean|lv] = (A A f) Wem + a1 (x) bem + bc ---
    k_f2h<<<(N * 64 + tb - 1) / tb, tb>>>(feature, hA, N * 64);
    k_aggh128<true><<<nBlkW, tb>>>(hA, hB, N);
    k_aggh128<false><<<nBlkW, tb>>>(hB, bufA, N);
    k_gemm_r1<128><<<gemmBlocks, tb, smem128r>>>(bufA, Wem, bc, bem, bufB, N);
    k_mlz<<<(N * 16 + tb - 1) / tb, tb>>>(bufB, noise, zout, mout, lvout, hA, N);

    // --- decoder collapsed: out = (A A z) Wdd + a1 (x) bdd + bd2 ---
    k_aggh64<true><<<nBlkW, tb>>>(hA, hB, N);
    k_aggh64<false><<<nBlkW, tb>>>(hB, bufA, N);
    k_gemm_r1<64><<<gemmBlocks, tb, smem64r>>>(bufA, Wdd, b_d2, bdd, oout, N);
}

// round 8
// speedup vs baseline: 1.1547x; 1.0002x over previous
#include <cuda_runtime.h>
#include <cuda_fp16.h>
#include <math.h>

// Problem-shape scratch (allocation-free rule: __device__ globals).
#define NMAX 50048
#define EMAX 1700000
#define SCAN_BLK 1024
#define MAX_SBLKS ((NMAX + SCAN_BLK - 1) / SCAN_BLK)

__device__ int    g_cnt[NMAX];
__device__ int    g_off[NMAX + 1];
__device__ int    g_cursor[NMAX];
__device__ int    g_bsum[MAX_SBLKS + 1];
__device__ float  g_dinv[NMAX];
__device__ float  g_a1[NMAX];        // A_norm * ones
__device__ int    g_eidx[EMAX];
__device__ float  g_ew[EMAX];
__device__ float  g_bufA[6500000];   // N x 128 fp32 scratch
__device__ float  g_bufB[6500000];   // N x 128 fp32 scratch
__device__ __half g_hA[6500000];     // N x 128 half scratch
__device__ __half g_hB[6500000];     // N x 128 half scratch
__device__ float  g_Wc[128 * 128];   // packed [W_mean | W_lv]
__device__ float  g_bc[128];         // packed [b_mean | b_lv]
__device__ float  g_Wem[128 * 128];  // W_enc @ Wc
__device__ float  g_bem[128];        // b_enc @ Wc
__device__ float  g_Wdd[64 * 128];   // W_d1 @ W_d2
__device__ float  g_bdd[128];        // b_d1 @ W_d2
__device__ float  g_zero[128];       // stays zero

// ---------------------------------------------------------------------------
// f32x2 packed-FMA helpers (FFMA2 — only reachable via PTX fma.rn.f32x2)
// ---------------------------------------------------------------------------
typedef unsigned long long u64;
__device__ __forceinline__ u64 bcast2(float s) {
    u64 r; asm("mov.b64 %0, {%1, %1};" : "=l"(r) : "f"(s)); return r;
}
__device__ __forceinline__ u64 pack2(float lo, float hi) {
    u64 r; asm("mov.b64 %0, {%1, %2};" : "=l"(r) : "f"(lo), "f"(hi)); return r;
}
__device__ __forceinline__ float2 unpack2(u64 v) {
    float2 f; asm("mov.b64 {%0, %1}, %2;" : "=f"(f.x), "=f"(f.y) : "l"(v)); return f;
}
__device__ __forceinline__ void fmaa2(u64& acc, u64 a, u64 b) {
    asm("fma.rn.f32x2 %0, %1, %2, %0;" : "+l"(acc) : "l"(a), "l"(b));
}

// ---------------------------------------------------------------------------
// CSR build
// ---------------------------------------------------------------------------
__global__ void k_count(const int* __restrict__ dst, int E) {
    int i = blockIdx.x * blockDim.x + threadIdx.x;
    if (i < E) atomicAdd(&g_cnt[dst[i]], 1);
}

__global__ void k_dinv(int n) {
    int i = blockIdx.x * blockDim.x + threadIdx.x;
    if (i < n) g_dinv[i] = rsqrtf((float)g_cnt[i] + 1.0f);
}

__global__ void k_scan_local(int n) {
    int b = blockIdx.x;
    int t = threadIdx.x;          // 256 threads
    int lane = t & 31, wid = t >> 5;
    int idx = b * SCAN_BLK + t * 4;
    int v0 = (idx + 0 < n) ? g_cnt[idx + 0] : 0;
    int v1 = (idx + 1 < n) ? g_cnt[idx + 1] : 0;
    int v2 = (idx + 2 < n) ? g_cnt[idx + 2] : 0;
    int v3 = (idx + 3 < n) ? g_cnt[idx + 3] : 0;
    int s = v0 + v1 + v2 + v3;
    int pre = s;
    #pragma unroll
    for (int d = 1; d < 32; d <<= 1) {
        int t2 = __shfl_up_sync(0xffffffffu, pre, d);
        if (lane >= d) pre += t2;
    }
    __shared__ int wsum[8];
    __shared__ int wexcl[8];
    if (lane == 31) wsum[wid] = pre;
    __syncthreads();
    if (t == 0) {
        int acc = 0;
        #pragma unroll
        for (int i = 0; i < 8; i++) { wexcl[i] = acc; acc += wsum[i]; }
        g_bsum[b] = acc;
    }
    __syncthreads();
    int run = (pre - s) + wexcl[wid];
    if (idx + 0 < n) g_off[idx + 0] = run;  run += v0;
    if (idx + 1 < n) g_off[idx + 1] = run;  run += v1;
    if (idx + 2 < n) g_off[idx + 2] = run;  run += v2;
    if (idx + 3 < n) g_off[idx + 3] = run;
}

__global__ void k_scan_bsums(int nb, int n) {
    __shared__ int sh[64];
    int t = threadIdx.x;           // 64 threads, nb <= 49
    int v = (t < nb) ? g_bsum[t] : 0;
    sh[t] = v;
    __syncthreads();
    #pragma unroll
    for (int ofs = 1; ofs < 64; ofs <<= 1) {
        int x = (t >= ofs) ? sh[t - ofs] : 0;
        __syncthreads();
        sh[t] += x;
        __syncthreads();
    }
    if (t < nb) g_bsum[t] = sh[t] - v;
    if (t == 63) g_off[n] = sh[63];
}

__global__ void k_scan_add(int n) {
    int i = blockIdx.x * blockDim.x + threadIdx.x;
    if (i < n) {
        int o = g_off[i] + g_bsum[i >> 10];
        g_off[i] = o;
        g_cursor[i] = o;
    }
}

__global__ void k_fill(const int* __restrict__ src, const int* __restrict__ dst, int E) {
    int e = blockIdx.x * blockDim.x + threadIdx.x;
    if (e < E) {
        int s = src[e], d = dst[e];
        int p = atomicAdd(&g_cursor[d], 1);
        g_eidx[p] = s;
        g_ew[p] = g_dinv[s] * g_dinv[d];
    }
}

__global__ void k_a1(int n) {
    int w = (blockIdx.x * blockDim.x + threadIdx.x) >> 5;
    int lane = threadIdx.x & 31;
    if (w >= n) return;
    float acc = 0.0f;
    int p = g_off[w] + lane, end = g_off[w + 1];
    for (; p < end; p += 32) acc += g_ew[p];
    #pragma unroll
    for (int d = 16; d; d >>= 1) acc += __shfl_down_sync(0xffffffffu, acc, d);
    if (lane == 0) {
        float di = g_dinv[w];
        g_a1[w] = acc + di * di;
    }
}

// ---------------------------------------------------------------------------
// fp32 -> fp16 convert
// ---------------------------------------------------------------------------
__global__ void k_f2h(const float* __restrict__ X, __half* __restrict__ H, int n2) {
    int i = blockIdx.x * blockDim.x + threadIdx.x;
    if (i < n2) {
        float2 v = ((const float2*)X)[i];
        ((__half2*)H)[i] = __floats2half2_rn(v.x, v.y);
    }
}

// ---------------------------------------------------------------------------
// Aggregation Y = A_norm * X, half inputs, fp32 accumulation.
// Unroll-8 with vectorized metadata loads (peel to 4-alignment).
// ---------------------------------------------------------------------------
__device__ __forceinline__ float4 h4_to_f4(float2 raw) {
    __half2 h0 = *reinterpret_cast<__half2*>(&raw.x);
    __half2 h1 = *reinterpret_cast<__half2*>(&raw.y);
    float2 f0 = __half22float2(h0);
    float2 f1 = __half22float2(h1);
    return make_float4(f0.x, f0.y, f1.x, f1.y);
}
__device__ __forceinline__ void acc4(float4& acc, float w, float4 a) {
    acc.x = fmaf(w, a.x, acc.x);
    acc.y = fmaf(w, a.y, acc.y);
    acc.z = fmaf(w, a.z, acc.z);
    acc.w = fmaf(w, a.w, acc.w);
}

template <bool OUTH>
__global__ void k_aggh128(const __half* __restrict__ X, void* __restrict__ Y, int n) {
    int w = (blockIdx.x * blockDim.x + threadIdx.x) >> 5;
    int lane = threadIdx.x & 31;
    if (w >= n) return;
    const float2* Xv = (const float2*)X;   // 4 halves per float2
    float di = g_dinv[w];
    float sw = di * di;
    float4 acc = h4_to_f4(Xv[(size_t)w * 32 + lane]);
    acc.x *= sw; acc.y *= sw; acc.z *= sw; acc.w *= sw;
    int p = g_off[w], end = g_off[w + 1];
    // peel to 4-alignment for vector metadata loads
    while (p < end && (p & 3)) {
        float wt = g_ew[p];
        acc4(acc, wt, h4_to_f4(Xv[(size_t)g_eidx[p] * 32 + lane]));
        p++;
    }
    for (; p + 8 <= end; p += 8) {
        int4   ia = *(const int4*)(g_eidx + p);
        int4   ib = *(const int4*)(g_eidx + p + 4);
        float4 wa = *(const float4*)(g_ew + p);
        float4 wb = *(const float4*)(g_ew + p + 4);
        float2 r0 = Xv[(size_t)ia.x * 32 + lane];
        float2 r1 = Xv[(size_t)ia.y * 32 + lane];
        float2 r2 = Xv[(size_t)ia.z * 32 + lane];
        float2 r3 = Xv[(size_t)ia.w * 32 + lane];
        float2 r4 = Xv[(size_t)ib.x * 32 + lane];
        float2 r5 = Xv[(size_t)ib.y * 32 + lane];
        float2 r6 = Xv[(size_t)ib.z * 32 + lane];
        float2 r7 = Xv[(size_t)ib.w * 32 + lane];
        acc4(acc, wa.x, h4_to_f4(r0));
        acc4(acc, wa.y, h4_to_f4(r1));
        acc4(acc, wa.z, h4_to_f4(r2));
        acc4(acc, wa.w, h4_to_f4(r3));
        acc4(acc, wb.x, h4_to_f4(r4));
        acc4(acc, wb.y, h4_to_f4(r5));
        acc4(acc, wb.z, h4_to_f4(r6));
        acc4(acc, wb.w, h4_to_f4(r7));
    }
    for (; p < end; p++) {
        float wt = g_ew[p];
        acc4(acc, wt, h4_to_f4(Xv[(size_t)g_eidx[p] * 32 + lane]));
    }
    if (OUTH) {
        float2 raw;
        *reinterpret_cast<__half2*>(&raw.x) = __floats2half2_rn(acc.x, acc.y);
        *reinterpret_cast<__half2*>(&raw.y) = __floats2half2_rn(acc.z, acc.w);
        ((float2*)Y)[(size_t)w * 32 + lane] = raw;
    } else {
        ((float4*)Y)[(size_t)w * 32 + lane] = acc;
    }
}

template <bool OUTH>
__global__ void k_aggh64(const __half* __restrict__ X, void* __restrict__ Y, int n) {
    int w = (blockIdx.x * blockDim.x + threadIdx.x) >> 5;
    int lane = threadIdx.x & 31;
    if (w >= n) return;
    const __half2* Xv = (const __half2*)X;
    float di = g_dinv[w];
    float sw = di * di;
    float2 acc = __half22float2(Xv[(size_t)w * 32 + lane]);
    acc.x *= sw; acc.y *= sw;
    int p = g_off[w], end = g_off[w + 1];
    while (p < end && (p & 3)) {
        float wt = g_ew[p];
        float2 a = __half22float2(Xv[(size_t)g_eidx[p] * 32 + lane]);
        acc.x = fmaf(wt, a.x, acc.x); acc.y = fmaf(wt, a.y, acc.y);
        p++;
    }
    for (; p + 8 <= end; p += 8) {
        int4   ia = *(const int4*)(g_eidx + p);
        int4   ib = *(const int4*)(g_eidx + p + 4);
        float4 wa = *(const float4*)(g_ew + p);
        float4 wb = *(const float4*)(g_ew + p + 4);
        __half2 r0 = Xv[(size_t)ia.x * 32 + lane];
        __half2 r1 = Xv[(size_t)ia.y * 32 + lane];
        __half2 r2 = Xv[(size_t)ia.z * 32 + lane];
        __half2 r3 = Xv[(size_t)ia.w * 32 + lane];
        __half2 r4 = Xv[(size_t)ib.x * 32 + lane];
        __half2 r5 = Xv[(size_t)ib.y * 32 + lane];
        __half2 r6 = Xv[(size_t)ib.z * 32 + lane];
        __half2 r7 = Xv[(size_t)ib.w * 32 + lane];
        float2 f;
        f = __half22float2(r0); acc.x = fmaf(wa.x, f.x, acc.x); acc.y = fmaf(wa.x, f.y, acc.y);
        f = __half22float2(r1); acc.x = fmaf(wa.y, f.x, acc.x); acc.y = fmaf(wa.y, f.y, acc.y);
        f = __half22float2(r2); acc.x = fmaf(wa.z, f.x, acc.x); acc.y = fmaf(wa.z, f.y, acc.y);
        f = __half22float2(r3); acc.x = fmaf(wa.w, f.x, acc.x); acc.y = fmaf(wa.w, f.y, acc.y);
        f = __half22float2(r4); acc.x = fmaf(wb.x, f.x, acc.x); acc.y = fmaf(wb.x, f.y, acc.y);
        f = __half22float2(r5); acc.x = fmaf(wb.y, f.x, acc.x); acc.y = fmaf(wb.y, f.y, acc.y);
        f = __half22float2(r6); acc.x = fmaf(wb.z, f.x, acc.x); acc.y = fmaf(wb.z, f.y, acc.y);
        f = __half22float2(r7); acc.x = fmaf(wb.w, f.x, acc.x); acc.y = fmaf(wb.w, f.y, acc.y);
    }
    for (; p < end; p++) {
        float wt = g_ew[p];
        float2 a = __half22float2(Xv[(size_t)g_eidx[p] * 32 + lane]);
        acc.x = fmaf(wt, a.x, acc.x); acc.y = fmaf(wt, a.y, acc.y);
    }
    if (OUTH) {
        ((__half2*)Y)[(size_t)w * 32 + lane] = __floats2half2_rn(acc.x, acc.y);
    } else {
        ((float2*)Y)[(size_t)w * 32 + lane] = acc;
    }
}

// ---------------------------------------------------------------------------
// GEMMs
// ---------------------------------------------------------------------------
__device__ __forceinline__ void fma4(float4& acc, float s, const float4& v) {
    acc.x = fmaf(s, v.x, acc.x);
    acc.y = fmaf(s, v.y, acc.y);
    acc.z = fmaf(s, v.z, acc.z);
    acc.w = fmaf(s, v.w, acc.w);
}

// Plain scalar GEMM (tiny weight-combine precomputes only)
template <int KDIM>
__global__ void k_gemm2(const float* __restrict__ X, const float* __restrict__ W,
                        const float* __restrict__ b, float* __restrict__ Y, int M) {
    extern __shared__ float sm[];
    float* sW = sm;
    float* sb = sm + KDIM * 128;
    for (int idx = threadIdx.x; idx < KDIM * 32; idx += blockDim.x)
        ((float4*)sW)[idx] = ((const float4*)W)[idx];
    if (threadIdx.x < 128) sb[threadIdx.x] = b[threadIdx.x];
    __syncthreads();

    int lane = threadIdx.x & 31;
    int wg = (blockIdx.x * blockDim.x + threadIdx.x) >> 5;
    int nw = (gridDim.x * blockDim.x) >> 5;
    for (int r0 = wg * 2; r0 < M; r0 += nw * 2) {
        int r1 = r0 + 1;
        bool has1 = (r1 < M);
        const float* x0 = X + (size_t)r0 * KDIM;
        const float* x1 = X + (size_t)(has1 ? r1 : r0) * KDIM;
        float4 acc0 = ((const float4*)sb)[lane];
        float4 acc1 = acc0;
        #pragma unroll 8
        for (int k = 0; k < KDIM; k += 4) {
            float4 a = *(const float4*)(x0 + k);
            float4 c = *(const float4*)(x1 + k);
            float4 w0 = ((const float4*)(sW + (size_t)(k + 0) * 128))[lane];
            float4 w1 = ((const float4*)(sW + (size_t)(k + 1) * 128))[lane];
            float4 w2 = ((const float4*)(sW + (size_t)(k + 2) * 128))[lane];
            float4 w3 = ((const float4*)(sW + (size_t)(k + 3) * 128))[lane];
            fma4(acc0, a.x, w0); fma4(acc1, c.x, w0);
            fma4(acc0, a.y, w1); fma4(acc1, c.y, w1);
            fma4(acc0, a.z, w2); fma4(acc1, c.z, w2);
            fma4(acc0, a.w, w3); fma4(acc1, c.w, w3);
        }
        *(float4*)(Y + (size_t)r0 * 128 + lane * 4) = acc0;
        if (has1) *(float4*)(Y + (size_t)r1 * 128 + lane * 4) = acc1;
    }
}

// Production GEMM, 4 rows/warp, f32x2 packed FMA: Y = X @ W + b + a1 (x) v
template <int KDIM>
__global__ void k_gemm_r1(const float* __restrict__ X, const float* __restrict__ W,
                          const float* __restrict__ b, const float* __restrict__ v,
                          float* __restrict__ Y, int M) {
    extern __shared__ float sm[];
    float* sW = sm;                 // KDIM * 128
    float* sb = sm + KDIM * 128;    // 128
    float* sv = sb + 128;           // 128
    for (int idx = threadIdx.x; idx < KDIM * 32; idx += blockDim.x)
        ((float4*)sW)[idx] = ((const float4*)W)[idx];
    if (threadIdx.x < 128) {
        sb[threadIdx.x] = b[threadIdx.x];
        sv[threadIdx.x] = v[threadIdx.x];
    }
    __syncthreads();

    const ulonglong2* sW2 = (const ulonglong2*)sW;
    int lane = threadIdx.x & 31;
    int wg = (blockIdx.x * blockDim.x + threadIdx.x) >> 5;
    int nw = (gridDim.x * blockDim.x) >> 5;
    for (int r0 = wg * 4; r0 < M; r0 += nw * 4) {
        int rr[4];
        rr[0] = r0;
        rr[1] = (r0 + 1 < M) ? r0 + 1 : r0;
        rr[2] = (r0 + 2 < M) ? r0 + 2 : r0;
        rr[3] = (r0 + 3 < M) ? r0 + 3 : r0;
        const float* xp[4];
        u64 accl[4], acch[4];
        float4 bb = ((const float4*)sb)[lane];
        float4 vv = ((const float4*)sv)[lane];
        #pragma unroll
        for (int i = 0; i < 4; i++) {
            xp[i] = X + (size_t)rr[i] * KDIM;
            float av = g_a1[rr[i]];
            accl[i] = pack2(fmaf(av, vv.x, bb.x), fmaf(av, vv.y, bb.y));
            acch[i] = pack2(fmaf(av, vv.z, bb.z), fmaf(av, vv.w, bb.w));
        }
        #pragma unroll 4
        for (int k = 0; k < KDIM; k += 4) {
            ulonglong2 w0 = sW2[(size_t)(k + 0) * 32 + lane];
            ulonglong2 w1 = sW2[(size_t)(k + 1) * 32 + lane];
            ulonglong2 w2 = sW2[(size_t)(k + 2) * 32 + lane];
            ulonglong2 w3 = sW2[(size_t)(k + 3) * 32 + lane];
            #pragma unroll
            for (int i = 0; i < 4; i++) {
                float4 a = *(const float4*)(xp[i] + k);
                u64 s;
                s = bcast2(a.x); fmaa2(accl[i], s, w0.x); fmaa2(acch[i], s, w0.y);
                s = bcast2(a.y); fmaa2(accl[i], s, w1.x); fmaa2(acch[i], s, w1.y);
                s = bcast2(a.z); fmaa2(accl[i], s, w2.x); fmaa2(acch[i], s, w2.y);
                s = bcast2(a.w); fmaa2(accl[i], s, w3.x); fmaa2(acch[i], s, w3.y);
            }
        }
        #pragma unroll
        for (int i = 0; i < 4; i++) {
            if (r0 + i < M) {
                float2 o0 = unpack2(accl[i]), o1 = unpack2(acch[i]);
                *(float4*)(Y + (size_t)(r0 + i) * 128 + lane * 4) =
                    make_float4(o0.x, o0.y, o1.x, o1.y);
            }
        }
    }
}

// Pack [W_mean | W_lv] into 128x128, same for bias.
__global__ void k_pack(const float* __restrict__ Wm, const float* __restrict__ Wl,
                       const float* __restrict__ bm, const float* __restrict__ bl) {
    int idx = blockIdx.x * blockDim.x + threadIdx.x;
    if (idx < 128 * 128) {
        int k = idx >> 7, c = idx & 127;
        g_Wc[idx] = (c < 64) ? Wm[k * 64 + c] : Wl[k * 64 + (c - 64)];
    }
    if (idx < 128) g_bc[idx] = (idx < 64) ? bm[idx] : bl[idx - 64];
}

// z = noise*exp(0.5*lv) + mean; split packed [mean|lv]; also emit half z.
__global__ void k_mlz(const float* __restrict__ ML, const float* __restrict__ noise,
                      float* __restrict__ z, float* __restrict__ m,
                      float* __restrict__ lv, __half* __restrict__ zh, int N) {
    int i = blockIdx.x * blockDim.x + threadIdx.x;  // over N*16 float4 groups
    if (i >= N * 16) return;
    int row = i >> 4, c4 = i & 15;
    float4 me  = *(const float4*)(ML + (size_t)row * 128 + c4 * 4);
    float4 lvv = *(const float4*)(ML + (size_t)row * 128 + 64 + c4 * 4);
    float4 nz  = ((const float4*)noise)[i];
    float4 zz;
    zz.x = fmaf(nz.x, expf(0.5f * lvv.x), me.x);
    zz.y = fmaf(nz.y, expf(0.5f * lvv.y), me.y);
    zz.z = fmaf(nz.z, expf(0.5f * lvv.z), me.z);
    zz.w = fmaf(nz.w, expf(0.5f * lvv.w), me.w);
    ((float4*)z)[i] = zz;
    ((float4*)m)[i] = me;
    ((float4*)lv)[i] = lvv;
    float2 raw;
    *reinterpret_cast<__half2*>(&raw.x) = __floats2half2_rn(zz.x, zz.y);
    *reinterpret_cast<__half2*>(&raw.y) = __floats2half2_rn(zz.z, zz.w);
    ((float2*)zh)[i] = raw;
}

// ---------------------------------------------------------------------------
extern "C" void kernel_launch(void* const* d_in, const int* in_sizes, int n_in,
                              void* d_out, int out_size) {
    const float* feature = (const float*)d_in[0];
    const int*   ei      = (const int*)d_in[1];
    const float* noise   = (const float*)d_in[2];
    const float* W_enc   = (const float*)d_in[3];
    const float* b_enc   = (const float*)d_in[4];
    const float* W_mean  = (const float*)d_in[5];
    const float* b_mean  = (const float*)d_in[6];
    const float* W_lv    = (const float*)d_in[7];
    const float* b_lv    = (const float*)d_in[8];
    const float* W_d1    = (const float*)d_in[9];
    const float* b_d1    = (const float*)d_in[10];
    const float* W_d2    = (const float*)d_in[11];
    const float* b_d2    = (const float*)d_in[12];

    int N = in_sizes[0] / 128;
    int E = in_sizes[1] / 2;
    const int* src = ei;
    const int* dst = ei + E;

    float* zout  = (float*)d_out;
    float* mout  = zout + (size_t)N * 64;
    float* lvout = mout + (size_t)N * 64;
    float* oout  = lvout + (size_t)N * 64;

    float *bufA, *bufB, *Wc, *bc, *Wem, *bem, *Wdd, *bdd, *zerov, *cntp;
    __half *hA, *hB;
    cudaGetSymbolAddress((void**)&cntp, g_cnt);
    cudaGetSymbolAddress((void**)&bufA, g_bufA);
    cudaGetSymbolAddress((void**)&bufB, g_bufB);
    cudaGetSymbolAddress((void**)&hA, g_hA);
    cudaGetSymbolAddress((void**)&hB, g_hB);
    cudaGetSymbolAddress((void**)&Wc, g_Wc);
    cudaGetSymbolAddress((void**)&bc, g_bc);
    cudaGetSymbolAddress((void**)&Wem, g_Wem);
    cudaGetSymbolAddress((void**)&bem, g_bem);
    cudaGetSymbolAddress((void**)&Wdd, g_Wdd);
    cudaGetSymbolAddress((void**)&bdd, g_bdd);
    cudaGetSymbolAddress((void**)&zerov, g_zero);

    const int smem128  = 128 * 128 * 4 + 512;
    const int smem128r = 128 * 128 * 4 + 1024;
    const int smem64r  = 64 * 128 * 4 + 1024;
    cudaFuncSetAttribute(k_gemm2<128>,   cudaFuncAttributeMaxDynamicSharedMemorySize, smem128);
    cudaFuncSetAttribute(k_gemm_r1<128>, cudaFuncAttributeMaxDynamicSharedMemorySize, smem128r);
    cudaFuncSetAttribute(k_gemm_r1<64>,  cudaFuncAttributeMaxDynamicSharedMemorySize, smem64r);

    int tb = 256;
    int nBlkN = (N + tb - 1) / tb;
    int nBlkE = (E + tb - 1) / tb;
    int nBlkW = (N * 32 + tb - 1) / tb;   // warp per node
    int nSBlks = (N + SCAN_BLK - 1) / SCAN_BLK;
    int gemmBlocks = 444;

    // --- CSR build ---
    cudaMemsetAsync(cntp, 0, (size_t)N * sizeof(int));
    k_count<<<nBlkE, tb>>>(dst, E);
    k_dinv<<<nBlkN, tb>>>(N);
    k_scan_local<<<nSBlks, 256>>>(N);
    k_scan_bsums<<<1, 64>>>(nSBlks, N);
    k_scan_add<<<nBlkN, tb>>>(N);
    k_fill<<<nBlkE, tb>>>(src, dst, E);
    k_a1<<<nBlkW, tb>>>(N);

    // --- weight precomputes (tiny) ---
    k_pack<<<(128 * 128 + tb - 1) / tb, tb>>>(W_mean, W_lv, b_mean, b_lv);
    k_gemm2<128><<<8, tb, smem128>>>(W_enc, Wc, zerov, Wem, 128);   // We @ Wc
    k_gemm2<128><<<1, tb, smem128>>>(b_enc, Wc, zerov, bem, 1);     // be @ Wc
    k_gemm2<128><<<4, tb, smem128>>>(W_d1, W_d2, zerov, Wdd, 64);   // Wd1 @ Wd2
    k_gemm2<128><<<1, tb, smem128>>>(b_d1, W_d2, zerov, bdd, 1);    // bd1 @ Wd2

    // --- encoder collapsed: [mean|lv] = (A A f) Wem + a1 (x) bem + bc ---
    k_f2h<<<(N * 64 + tb - 1) / tb, tb>>>(feature, hA, N * 64);
    k_aggh128<true><<<nBlkW, tb>>>(hA, hB, N);
    k_aggh128<false><<<nBlkW, tb>>>(hB, bufA, N);
    k_gemm_r1<128><<<gemmBlocks, tb, smem128r>>>(bufA, Wem, bc, bem, bufB, N);
    k_mlz<<<(N * 16 + tb - 1) / tb, tb>>>(bufB, noise, zout, mout, lvout, hA, N);

    // --- decoder collapsed: out = (A A z) Wdd + a1 (x) bdd + bd2 ---
    k_aggh64<true><<<nBlkW, tb>>>(hA, hB, N);
    k_aggh64<false><<<nBlkW, tb>>>(hB, bufA, N);
    k_gemm_r1<64><<<gemmBlocks, tb, smem64r>>>(bufA, Wdd, b_d2, bdd, oout, N);
}

// round 9
// speedup vs baseline: 1.2608x; 1.0919x over previous
#include <cuda_runtime.h>
#include <cuda_fp16.h>
#include <math.h>

// Problem-shape scratch (allocation-free rule: __device__ globals).
#define NMAX 50048
#define EMAX 1700000
#define SCAN_BLK 1024
#define MAX_SBLKS ((NMAX + SCAN_BLK - 1) / SCAN_BLK)

__device__ int    g_cnt[NMAX];
__device__ int    g_off[NMAX + 1];
__device__ int    g_cursor[NMAX];
__device__ int    g_bsum[MAX_SBLKS + 1];
__device__ float  g_dinv[NMAX];
__device__ float  g_a1[NMAX];        // A_norm * ones
__device__ int    g_eidx[EMAX];
__device__ float  g_ew[EMAX];
__device__ float  g_bufA[6500000];   // N x 128 fp32 scratch
__device__ __half g_hA[6500000];     // N x 128 half scratch
__device__ __half g_hB[6500000];     // N x 128 half scratch
__device__ float  g_Wem[128 * 128];  // W_enc @ [W_mean|W_lv]
__device__ float  g_bem[128];        // b_enc @ [W_mean|W_lv]
__device__ float  g_Wdd[64 * 128];   // W_d1 @ W_d2
__device__ float  g_bdd[128];        // b_d1 @ W_d2
__device__ float  g_bc[128];         // packed [b_mean | b_lv]

// ---------------------------------------------------------------------------
// f32x2 packed-FMA helpers (FFMA2 — only reachable via PTX fma.rn.f32x2)
// ---------------------------------------------------------------------------
typedef unsigned long long u64;
__device__ __forceinline__ u64 bcast2(float s) {
    u64 r; asm("mov.b64 %0, {%1, %1};" : "=l"(r) : "f"(s)); return r;
}
__device__ __forceinline__ u64 pack2(float lo, float hi) {
    u64 r; asm("mov.b64 %0, {%1, %2};" : "=l"(r) : "f"(lo), "f"(hi)); return r;
}
__device__ __forceinline__ float2 unpack2(u64 v) {
    float2 f; asm("mov.b64 {%0, %1}, %2;" : "=f"(f.x), "=f"(f.y) : "l"(v)); return f;
}
__device__ __forceinline__ void fmaa2(u64& acc, u64 a, u64 b) {
    asm("fma.rn.f32x2 %0, %1, %2, %0;" : "+l"(acc) : "l"(a), "l"(b));
}

// ---------------------------------------------------------------------------
// CSR build
// ---------------------------------------------------------------------------
__global__ void k_count(const int* __restrict__ dst, int E) {
    int i = blockIdx.x * blockDim.x + threadIdx.x;
    if (i < E) atomicAdd(&g_cnt[dst[i]], 1);
}

// local scan + dinv (cnt already loaded here)
__global__ void k_scan_local(int n) {
    int b = blockIdx.x;
    int t = threadIdx.x;          // 256 threads
    int lane = t & 31, wid = t >> 5;
    int idx = b * SCAN_BLK + t * 4;
    int v0 = (idx + 0 < n) ? g_cnt[idx + 0] : 0;
    int v1 = (idx + 1 < n) ? g_cnt[idx + 1] : 0;
    int v2 = (idx + 2 < n) ? g_cnt[idx + 2] : 0;
    int v3 = (idx + 3 < n) ? g_cnt[idx + 3] : 0;
    if (idx + 0 < n) g_dinv[idx + 0] = rsqrtf((float)v0 + 1.0f);
    if (idx + 1 < n) g_dinv[idx + 1] = rsqrtf((float)v1 + 1.0f);
    if (idx + 2 < n) g_dinv[idx + 2] = rsqrtf((float)v2 + 1.0f);
    if (idx + 3 < n) g_dinv[idx + 3] = rsqrtf((float)v3 + 1.0f);
    int s = v0 + v1 + v2 + v3;
    int pre = s;
    #pragma unroll
    for (int d = 1; d < 32; d <<= 1) {
        int t2 = __shfl_up_sync(0xffffffffu, pre, d);
        if (lane >= d) pre += t2;
    }
    __shared__ int wsum[8];
    __shared__ int wexcl[8];
    if (lane == 31) wsum[wid] = pre;
    __syncthreads();
    if (t == 0) {
        int acc = 0;
        #pragma unroll
        for (int i = 0; i < 8; i++) { wexcl[i] = acc; acc += wsum[i]; }
        g_bsum[b] = acc;
    }
    __syncthreads();
    int run = (pre - s) + wexcl[wid];
    if (idx + 0 < n) g_off[idx + 0] = run;  run += v0;
    if (idx + 1 < n) g_off[idx + 1] = run;  run += v1;
    if (idx + 2 < n) g_off[idx + 2] = run;  run += v2;
    if (idx + 3 < n) g_off[idx + 3] = run;
}

__global__ void k_scan_bsums(int nb, int n) {
    __shared__ int sh[64];
    int t = threadIdx.x;           // 64 threads, nb <= 49
    int v = (t < nb) ? g_bsum[t] : 0;
    sh[t] = v;
    __syncthreads();
    #pragma unroll
    for (int ofs = 1; ofs < 64; ofs <<= 1) {
        int x = (t >= ofs) ? sh[t - ofs] : 0;
        __syncthreads();
        sh[t] += x;
        __syncthreads();
    }
    if (t < nb) g_bsum[t] = sh[t] - v;
    if (t == 63) g_off[n] = sh[63];
}

// finalize offsets, init cursor and a1 = dinv^2 (self-loop term)
__global__ void k_scan_add(int n) {
    int i = blockIdx.x * blockDim.x + threadIdx.x;
    if (i < n) {
        int o = g_off[i] + g_bsum[i >> 10];
        g_off[i] = o;
        g_cursor[i] = o;
        float di = g_dinv[i];
        g_a1[i] = di * di;
    }
}

// fill CSR + accumulate a1 (row sums of A_norm) via float atomics
__global__ void k_fill(const int* __restrict__ src, const int* __restrict__ dst, int E) {
    int e = blockIdx.x * blockDim.x + threadIdx.x;
    if (e < E) {
        int s = src[e], d = dst[e];
        float w = g_dinv[s] * g_dinv[d];
        int p = atomicAdd(&g_cursor[d], 1);
        g_eidx[p] = s;
        g_ew[p] = w;
        atomicAdd(&g_a1[d], w);
    }
}

// ---------------------------------------------------------------------------
// Weight precompute (single kernel): Wem/bem, Wdd/bdd, bc
//   Wem[r][c] = sum_j W_enc[r][j] * Wc[j][c],  Wc[j][c] = c<64 ? W_mean : W_lv
//   bem[c]    = sum_j b_enc[j]    * Wc[j][c]
//   Wdd[r][c] = sum_j W_d1[r][j]  * W_d2[j][c]
//   bdd[c]    = sum_j b_d1[j]     * W_d2[j][c]
//   bc[c]     = c<64 ? b_mean[c] : b_lv[c-64]
// ---------------------------------------------------------------------------
__global__ void k_wpre(const float* __restrict__ W_enc, const float* __restrict__ b_enc,
                       const float* __restrict__ W_mean, const float* __restrict__ W_lv,
                       const float* __restrict__ b_mean, const float* __restrict__ b_lv,
                       const float* __restrict__ W_d1, const float* __restrict__ b_d1,
                       const float* __restrict__ W_d2) {
    int idx = blockIdx.x * blockDim.x + threadIdx.x;
    if (idx < 129 * 128) {
        int r = idx >> 7, c = idx & 127;
        const float* arow = (r < 128) ? (W_enc + r * 128) : b_enc;
        const float* bcol = (c < 64) ? (W_mean + c) : (W_lv + (c - 64));
        float s = 0.0f;
        #pragma unroll 8
        for (int j = 0; j < 128; j++) s = fmaf(arow[j], bcol[j * 64], s);
        if (r < 128) g_Wem[r * 128 + c] = s; else g_bem[c] = s;
    } else if (idx < 129 * 128 + 65 * 128) {
        int t = idx - 129 * 128;
        int r = t >> 7, c = t & 127;
        const float* arow = (r < 64) ? (W_d1 + r * 128) : b_d1;
        float s = 0.0f;
        #pragma unroll 8
        for (int j = 0; j < 128; j++) s = fmaf(arow[j], W_d2[j * 128 + c], s);
        if (r < 64) g_Wdd[r * 128 + c] = s; else g_bdd[c] = s;
    } else if (idx < 129 * 128 + 65 * 128 + 128) {
        int c = idx - (129 * 128 + 65 * 128);
        g_bc[c] = (c < 64) ? b_mean[c] : b_lv[c - 64];
    }
}

// ---------------------------------------------------------------------------
// fp32 -> fp16 convert
// ---------------------------------------------------------------------------
__global__ void k_f2h(const float* __restrict__ X, __half* __restrict__ H, int n2) {
    int i = blockIdx.x * blockDim.x + threadIdx.x;
    if (i < n2) {
        float2 v = ((const float2*)X)[i];
        ((__half2*)H)[i] = __floats2half2_rn(v.x, v.y);
    }
}

// ---------------------------------------------------------------------------
// Aggregation Y = A_norm * X, half inputs, fp32 accumulation, unroll-8.
// ---------------------------------------------------------------------------
__device__ __forceinline__ float4 h4_to_f4(float2 raw) {
    __half2 h0 = *reinterpret_cast<__half2*>(&raw.x);
    __half2 h1 = *reinterpret_cast<__half2*>(&raw.y);
    float2 f0 = __half22float2(h0);
    float2 f1 = __half22float2(h1);
    return make_float4(f0.x, f0.y, f1.x, f1.y);
}
__device__ __forceinline__ void acc4(float4& acc, float w, float4 a) {
    acc.x = fmaf(w, a.x, acc.x);
    acc.y = fmaf(w, a.y, acc.y);
    acc.z = fmaf(w, a.z, acc.z);
    acc.w = fmaf(w, a.w, acc.w);
}

template <bool OUTH>
__global__ void k_aggh128(const __half* __restrict__ X, void* __restrict__ Y, int n) {
    int w = (blockIdx.x * blockDim.x + threadIdx.x) >> 5;
    int lane = threadIdx.x & 31;
    if (w >= n) return;
    const float2* Xv = (const float2*)X;   // 4 halves per float2
    float di = g_dinv[w];
    float sw = di * di;
    float4 acc = h4_to_f4(Xv[(size_t)w * 32 + lane]);
    acc.x *= sw; acc.y *= sw; acc.z *= sw; acc.w *= sw;
    int p = g_off[w], end = g_off[w + 1];
    while (p < end && (p & 3)) {
        float wt = g_ew[p];
        acc4(acc, wt, h4_to_f4(Xv[(size_t)g_eidx[p] * 32 + lane]));
        p++;
    }
    for (; p + 8 <= end; p += 8) {
        int4   ia = *(const int4*)(g_eidx + p);
        int4   ib = *(const int4*)(g_eidx + p + 4);
        float4 wa = *(const float4*)(g_ew + p);
        float4 wb = *(const float4*)(g_ew + p + 4);
        float2 r0 = Xv[(size_t)ia.x * 32 + lane];
        float2 r1 = Xv[(size_t)ia.y * 32 + lane];
        float2 r2 = Xv[(size_t)ia.z * 32 + lane];
        float2 r3 = Xv[(size_t)ia.w * 32 + lane];
        float2 r4 = Xv[(size_t)ib.x * 32 + lane];
        float2 r5 = Xv[(size_t)ib.y * 32 + lane];
        float2 r6 = Xv[(size_t)ib.z * 32 + lane];
        float2 r7 = Xv[(size_t)ib.w * 32 + lane];
        acc4(acc, wa.x, h4_to_f4(r0));
        acc4(acc, wa.y, h4_to_f4(r1));
        acc4(acc, wa.z, h4_to_f4(r2));
        acc4(acc, wa.w, h4_to_f4(r3));
        acc4(acc, wb.x, h4_to_f4(r4));
        acc4(acc, wb.y, h4_to_f4(r5));
        acc4(acc, wb.z, h4_to_f4(r6));
        acc4(acc, wb.w, h4_to_f4(r7));
    }
    for (; p < end; p++) {
        float wt = g_ew[p];
        acc4(acc, wt, h4_to_f4(Xv[(size_t)g_eidx[p] * 32 + lane]));
    }
    if (OUTH) {
        float2 raw;
        *reinterpret_cast<__half2*>(&raw.x) = __floats2half2_rn(acc.x, acc.y);
        *reinterpret_cast<__half2*>(&raw.y) = __floats2half2_rn(acc.z, acc.w);
        ((float2*)Y)[(size_t)w * 32 + lane] = raw;
    } else {
        ((float4*)Y)[(size_t)w * 32 + lane] = acc;
    }
}

template <bool OUTH>
__global__ void k_aggh64(const __half* __restrict__ X, void* __restrict__ Y, int n) {
    int w = (blockIdx.x * blockDim.x + threadIdx.x) >> 5;
    int lane = threadIdx.x & 31;
    if (w >= n) return;
    const __half2* Xv = (const __half2*)X;
    float di = g_dinv[w];
    float sw = di * di;
    float2 acc = __half22float2(Xv[(size_t)w * 32 + lane]);
    acc.x *= sw; acc.y *= sw;
    int p = g_off[w], end = g_off[w + 1];
    while (p < end && (p & 3)) {
        float wt = g_ew[p];
        float2 a = __half22float2(Xv[(size_t)g_eidx[p] * 32 + lane]);
        acc.x = fmaf(wt, a.x, acc.x); acc.y = fmaf(wt, a.y, acc.y);
        p++;
    }
    for (; p + 8 <= end; p += 8) {
        int4   ia = *(const int4*)(g_eidx + p);
        int4   ib = *(const int4*)(g_eidx + p + 4);
        float4 wa = *(const float4*)(g_ew + p);
        float4 wb = *(const float4*)(g_ew + p + 4);
        __half2 r0 = Xv[(size_t)ia.x * 32 + lane];
        __half2 r1 = Xv[(size_t)ia.y * 32 + lane];
        __half2 r2 = Xv[(size_t)ia.z * 32 + lane];
        __half2 r3 = Xv[(size_t)ia.w * 32 + lane];
        __half2 r4 = Xv[(size_t)ib.x * 32 + lane];
        __half2 r5 = Xv[(size_t)ib.y * 32 + lane];
        __half2 r6 = Xv[(size_t)ib.z * 32 + lane];
        __half2 r7 = Xv[(size_t)ib.w * 32 + lane];
        float2 f;
        f = __half22float2(r0); acc.x = fmaf(wa.x, f.x, acc.x); acc.y = fmaf(wa.x, f.y, acc.y);
        f = __half22float2(r1); acc.x = fmaf(wa.y, f.x, acc.x); acc.y = fmaf(wa.y, f.y, acc.y);
        f = __half22float2(r2); acc.x = fmaf(wa.z, f.x, acc.x); acc.y = fmaf(wa.z, f.y, acc.y);
        f = __half22float2(r3); acc.x = fmaf(wa.w, f.x, acc.x); acc.y = fmaf(wa.w, f.y, acc.y);
        f = __half22float2(r4); acc.x = fmaf(wb.x, f.x, acc.x); acc.y = fmaf(wb.x, f.y, acc.y);
        f = __half22float2(r5); acc.x = fmaf(wb.y, f.x, acc.x); acc.y = fmaf(wb.y, f.y, acc.y);
        f = __half22float2(r6); acc.x = fmaf(wb.z, f.x, acc.x); acc.y = fmaf(wb.z, f.y, acc.y);
        f = __half22float2(r7); acc.x = fmaf(wb.w, f.x, acc.x); acc.y = fmaf(wb.w, f.y, acc.y);
    }
    for (; p < end; p++) {
        float wt = g_ew[p];
        float2 a = __half22float2(Xv[(size_t)g_eidx[p] * 32 + lane]);
        acc.x = fmaf(wt, a.x, acc.x); acc.y = fmaf(wt, a.y, acc.y);
    }
    if (OUTH) {
        ((__half2*)Y)[(size_t)w * 32 + lane] = __floats2half2_rn(acc.x, acc.y);
    } else {
        ((float2*)Y)[(size_t)w * 32 + lane] = acc;
    }
}

// ---------------------------------------------------------------------------
// Decoder GEMM, 4 rows/warp, f32x2 packed FMA: Y = X @ W + b + a1 (x) v
// ---------------------------------------------------------------------------
template <int KDIM>
__global__ void k_gemm_r1(const float* __restrict__ X, const float* __restrict__ W,
                          const float* __restrict__ b, const float* __restrict__ v,
                          float* __restrict__ Y, int M) {
    extern __shared__ float sm[];
    float* sW = sm;                 // KDIM * 128
    float* sb = sm + KDIM * 128;    // 128
    float* sv = sb + 128;           // 128
    for (int idx = threadIdx.x; idx < KDIM * 32; idx += blockDim.x)
        ((float4*)sW)[idx] = ((const float4*)W)[idx];
    if (threadIdx.x < 128) {
        sb[threadIdx.x] = b[threadIdx.x];
        sv[threadIdx.x] = v[threadIdx.x];
    }
    __syncthreads();

    const ulonglong2* sW2 = (const ulonglong2*)sW;
    int lane = threadIdx.x & 31;
    int wg = (blockIdx.x * blockDim.x + threadIdx.x) >> 5;
    int nw = (gridDim.x * blockDim.x) >> 5;
    for (int r0 = wg * 4; r0 < M; r0 += nw * 4) {
        int rr[4];
        rr[0] = r0;
        rr[1] = (r0 + 1 < M) ? r0 + 1 : r0;
        rr[2] = (r0 + 2 < M) ? r0 + 2 : r0;
        rr[3] = (r0 + 3 < M) ? r0 + 3 : r0;
        const float* xp[4];
        u64 accl[4], acch[4];
        float4 bb = ((const float4*)sb)[lane];
        float4 vv = ((const float4*)sv)[lane];
        #pragma unroll
        for (int i = 0; i < 4; i++) {
            xp[i] = X + (size_t)rr[i] * KDIM;
            float av = g_a1[rr[i]];
            accl[i] = pack2(fmaf(av, vv.x, bb.x), fmaf(av, vv.y, bb.y));
            acch[i] = pack2(fmaf(av, vv.z, bb.z), fmaf(av, vv.w, bb.w));
        }
        #pragma unroll 4
        for (int k = 0; k < KDIM; k += 4) {
            ulonglong2 w0 = sW2[(size_t)(k + 0) * 32 + lane];
            ulonglong2 w1 = sW2[(size_t)(k + 1) * 32 + lane];
            ulonglong2 w2 = sW2[(size_t)(k + 2) * 32 + lane];
            ulonglong2 w3 = sW2[(size_t)(k + 3) * 32 + lane];
            #pragma unroll
            for (int i = 0; i < 4; i++) {
                float4 a = *(const float4*)(xp[i] + k);
                u64 s;
                s = bcast2(a.x); fmaa2(accl[i], s, w0.x); fmaa2(acch[i], s, w0.y);
                s = bcast2(a.y); fmaa2(accl[i], s, w1.x); fmaa2(acch[i], s, w1.y);
                s = bcast2(a.z); fmaa2(accl[i], s, w2.x); fmaa2(acch[i], s, w2.y);
                s = bcast2(a.w); fmaa2(accl[i], s, w3.x); fmaa2(acch[i], s, w3.y);
            }
        }
        #pragma unroll
        for (int i = 0; i < 4; i++) {
            if (r0 + i < M) {
                float2 o0 = unpack2(accl[i]), o1 = unpack2(acch[i]);
                *(float4*)(Y + (size_t)(r0 + i) * 128 + lane * 4) =
                    make_float4(o0.x, o0.y, o1.x, o1.y);
            }
        }
    }
}

// ---------------------------------------------------------------------------
// Encoder GEMM with fused reparameterization epilogue.
//   [mean|lv] = X @ Wem + bc + a1 (x) bem   (cols 0-63 mean, 64-127 lv)
//   z = noise * exp(0.5*lv) + mean
// Lanes 0-15 hold mean cols, lanes 16-31 hold lv cols; pair via shfl.xor 16.
// ---------------------------------------------------------------------------
__global__ void k_gemm_enc(const float* __restrict__ X, const float* __restrict__ W,
                           const float* __restrict__ b, const float* __restrict__ v,
                           const float* __restrict__ noise,
                           float* __restrict__ z, float* __restrict__ m,
                           float* __restrict__ lv, __half* __restrict__ zh, int M) {
    extern __shared__ float sm[];
    float* sW = sm;                 // 128 * 128
    float* sb = sm + 128 * 128;     // 128
    float* sv = sb + 128;           // 128
    for (int idx = threadIdx.x; idx < 128 * 32; idx += blockDim.x)
        ((float4*)sW)[idx] = ((const float4*)W)[idx];
    if (threadIdx.x < 128) {
        sb[threadIdx.x] = b[threadIdx.x];
        sv[threadIdx.x] = v[threadIdx.x];
    }
    __syncthreads();

    const ulonglong2* sW2 = (const ulonglong2*)sW;
    int lane = threadIdx.x & 31;
    int wg = (blockIdx.x * blockDim.x + threadIdx.x) >> 5;
    int nw = (gridDim.x * blockDim.x) >> 5;
    for (int r0 = wg * 4; r0 < M; r0 += nw * 4) {
        int rr[4];
        rr[0] = r0;
        rr[1] = (r0 + 1 < M) ? r0 + 1 : r0;
        rr[2] = (r0 + 2 < M) ? r0 + 2 : r0;
        rr[3] = (r0 + 3 < M) ? r0 + 3 : r0;
        const float* xp[4];
        u64 accl[4], acch[4];
        float4 bb = ((const float4*)sb)[lane];
        float4 vv = ((const float4*)sv)[lane];
        #pragma unroll
        for (int i = 0; i < 4; i++) {
            xp[i] = X + (size_t)rr[i] * 128;
            float av = g_a1[rr[i]];
            accl[i] = pack2(fmaf(av, vv.x, bb.x), fmaf(av, vv.y, bb.y));
            acch[i] = pack2(fmaf(av, vv.z, bb.z), fmaf(av, vv.w, bb.w));
        }
        #pragma unroll 4
        for (int k = 0; k < 128; k += 4) {
            ulonglong2 w0 = sW2[(size_t)(k + 0) * 32 + lane];
            ulonglong2 w1 = sW2[(size_t)(k + 1) * 32 + lane];
            ulonglong2 w2 = sW2[(size_t)(k + 2) * 32 + lane];
            ulonglong2 w3 = sW2[(size_t)(k + 3) * 32 + lane];
            #pragma unroll
            for (int i = 0; i < 4; i++) {
                float4 a = *(const float4*)(xp[i] + k);
                u64 s;
                s = bcast2(a.x); fmaa2(accl[i], s, w0.x); fmaa2(acch[i], s, w0.y);
                s = bcast2(a.y); fmaa2(accl[i], s, w1.x); fmaa2(acch[i], s, w1.y);
                s = bcast2(a.z); fmaa2(accl[i], s, w2.x); fmaa2(acch[i], s, w2.y);
                s = bcast2(a.w); fmaa2(accl[i], s, w3.x); fmaa2(acch[i], s, w3.y);
            }
        }
        #pragma unroll
        for (int i = 0; i < 4; i++) {
            int r = r0 + i;
            if (r >= M) break;   // uniform across warp
            float2 lo = unpack2(accl[i]), hi = unpack2(acch[i]);
            float4 val = make_float4(lo.x, lo.y, hi.x, hi.y);
            float4 pv;
            pv.x = __shfl_xor_sync(0xffffffffu, val.x, 16);
            pv.y = __shfl_xor_sync(0xffffffffu, val.y, 16);
            pv.z = __shfl_xor_sync(0xffffffffu, val.z, 16);
            pv.w = __shfl_xor_sync(0xffffffffu, val.w, 16);
            if (lane < 16) {
                // val = mean cols [4*lane .. 4*lane+3], pv = matching logvar
                ((float4*)m)[(size_t)r * 16 + lane] = val;
                float4 nz = ((const float4*)noise)[(size_t)r * 16 + lane];
                float4 zz;
                zz.x = fmaf(nz.x, expf(0.5f * pv.x), val.x);
                zz.y = fmaf(nz.y, expf(0.5f * pv.y), val.y);
                zz.z = fmaf(nz.z, expf(0.5f * pv.z), val.z);
                zz.w = fmaf(nz.w, expf(0.5f * pv.w), val.w);
                ((float4*)z)[(size_t)r * 16 + lane] = zz;
                float2 raw;
                *reinterpret_cast<__half2*>(&raw.x) = __floats2half2_rn(zz.x, zz.y);
                *reinterpret_cast<__half2*>(&raw.y) = __floats2half2_rn(zz.z, zz.w);
                ((float2*)zh)[(size_t)r * 16 + lane] = raw;
            } else {
                // val = logvar cols [4*(lane-16) ..]
                ((float4*)lv)[(size_t)r * 16 + (lane - 16)] = val;
            }
        }
    }
}

// ---------------------------------------------------------------------------
extern "C" void kernel_launch(void* const* d_in, const int* in_sizes, int n_in,
                              void* d_out, int out_size) {
    const float* feature = (const float*)d_in[0];
    const int*   ei      = (const int*)d_in[1];
    const float* noise   = (const float*)d_in[2];
    const float* W_enc   = (const float*)d_in[3];
    const float* b_enc   = (const float*)d_in[4];
    const float* W_mean  = (const float*)d_in[5];
    const float* b_mean  = (const float*)d_in[6];
    const float* W_lv    = (const float*)d_in[7];
    const float* b_lv    = (const float*)d_in[8];
    const float* W_d1    = (const float*)d_in[9];
    const float* b_d1    = (const float*)d_in[10];
    const float* W_d2    = (const float*)d_in[11];
    const float* b_d2    = (const float*)d_in[12];

    int N = in_sizes[0] / 128;
    int E = in_sizes[1] / 2;
    const int* src = ei;
    const int* dst = ei + E;

    float* zout  = (float*)d_out;
    float* mout  = zout + (size_t)N * 64;
    float* lvout = mout + (size_t)N * 64;
    float* oout  = lvout + (size_t)N * 64;

    float *bufA, *Wem, *bem, *Wdd, *bdd, *bc, *cntp;
    __half *hA, *hB;
    cudaGetSymbolAddress((void**)&cntp, g_cnt);
    cudaGetSymbolAddress((void**)&bufA, g_bufA);
    cudaGetSymbolAddress((void**)&hA, g_hA);
    cudaGetSymbolAddress((void**)&hB, g_hB);
    cudaGetSymbolAddress((void**)&Wem, g_Wem);
    cudaGetSymbolAddress((void**)&bem, g_bem);
    cudaGetSymbolAddress((void**)&Wdd, g_Wdd);
    cudaGetSymbolAddress((void**)&bdd, g_bdd);
    cudaGetSymbolAddress((void**)&bc, g_bc);

    const int smem128r = 128 * 128 * 4 + 1024;
    const int smem64r  = 64 * 128 * 4 + 1024;
    cudaFuncSetAttribute(k_gemm_enc,     cudaFuncAttributeMaxDynamicSharedMemorySize, smem128r);
    cudaFuncSetAttribute(k_gemm_r1<64>,  cudaFuncAttributeMaxDynamicSharedMemorySize, smem64r);

    int tb = 256;
    int nBlkN = (N + tb - 1) / tb;
    int nBlkE = (E + tb - 1) / tb;
    int nBlkW = (N * 32 + tb - 1) / tb;   // warp per node
    int nSBlks = (N + SCAN_BLK - 1) / SCAN_BLK;
    int gemmBlocks = 444;

    // --- CSR build (dinv folded into scan_local; a1 folded into scan_add/fill) ---
    cudaMemsetAsync(cntp, 0, (size_t)N * sizeof(int));
    k_count<<<nBlkE, tb>>>(dst, E);
    k_scan_local<<<nSBlks, 256>>>(N);
    k_scan_bsums<<<1, 64>>>(nSBlks, N);
    k_scan_add<<<nBlkN, tb>>>(N);
    k_fill<<<nBlkE, tb>>>(src, dst, E);

    // --- weight precompute: one kernel for Wem/bem, Wdd/bdd, bc ---
    k_wpre<<<(129 * 128 + 65 * 128 + 128 + tb - 1) / tb, tb>>>(
        W_enc, b_enc, W_mean, W_lv, b_mean, b_lv, W_d1, b_d1, W_d2);

    // --- encoder collapsed: [mean|lv] = (A A f) Wem + a1 (x) bem + bc; fused z ---
    k_f2h<<<(N * 64 + tb - 1) / tb, tb>>>(feature, hA, N * 64);
    k_aggh128<true><<<nBlkW, tb>>>(hA, hB, N);
    k_aggh128<false><<<nBlkW, tb>>>(hB, bufA, N);
    k_gemm_enc<<<gemmBlocks, tb, smem128r>>>(bufA, Wem, bc, bem, noise,
                                             zout, mout, lvout, hA, N);

    // --- decoder collapsed: out = (A A z) Wdd + a1 (x) bdd + bd2 ---
    k_aggh64<true><<<nBlkW, tb>>>(hA, hB, N);
    k_aggh64<false><<<nBlkW, tb>>>(hB, bufA, N);
    k_gemm_r1<64><<<gemmBlocks, tb, smem64r>>>(bufA, Wdd, b_d2, bdd, oout, N);
}

// round 10
// speedup vs baseline: 1.2711x; 1.0082x over previous
#include <cuda_runtime.h>
#include <cuda_fp16.h>
#include <math.h>

// Problem-shape scratch (allocation-free rule: __device__ globals).
#define NMAX 50048
#define EMAX 1700000
#define SCAN_BLK 1024
#define MAX_SBLKS ((NMAX + SCAN_BLK - 1) / SCAN_BLK)

__device__ int    g_cnt[NMAX];
__device__ int    g_off[NMAX + 1];
__device__ int    g_cursor[NMAX];
__device__ int    g_bsum[MAX_SBLKS + 1];
__device__ float  g_dinv[NMAX];
__device__ float  g_a1[NMAX];            // A_norm * ones
__device__ unsigned short g_eidx[EMAX];  // u16 node index (N < 65536)
__device__ float  g_bufA[6500000];       // N x 128 fp32 scratch
__device__ __half g_hA[6500000];         // N x 128 half scratch
__device__ __half g_hB[6500000];         // N x 128 half scratch
__device__ float  g_Wem[128 * 128];      // W_enc @ [W_mean|W_lv]
__device__ float  g_bem[128];            // b_enc @ [W_mean|W_lv]
__device__ float  g_Wdd[64 * 128];       // W_d1 @ W_d2
__device__ float  g_bdd[128];            // b_d1 @ W_d2
__device__ float  g_bc[128];             // packed [b_mean | b_lv]

// ---------------------------------------------------------------------------
// f32x2 packed-FMA helpers
// ---------------------------------------------------------------------------
typedef unsigned long long u64;
__device__ __forceinline__ u64 bcast2(float s) {
    u64 r; asm("mov.b64 %0, {%1, %1};" : "=l"(r) : "f"(s)); return r;
}
__device__ __forceinline__ u64 pack2(float lo, float hi) {
    u64 r; asm("mov.b64 %0, {%1, %2};" : "=l"(r) : "f"(lo), "f"(hi)); return r;
}
__device__ __forceinline__ float2 unpack2(u64 v) {
    float2 f; asm("mov.b64 {%0, %1}, %2;" : "=f"(f.x), "=f"(f.y) : "l"(v)); return f;
}
__device__ __forceinline__ void fmaa2(u64& acc, u64 a, u64 b) {
    asm("fma.rn.f32x2 %0, %1, %2, %0;" : "+l"(acc) : "l"(a), "l"(b));
}

// ---------------------------------------------------------------------------
// CSR build
// ---------------------------------------------------------------------------
__global__ void k_count(const int* __restrict__ dst, int E) {
    int i = blockIdx.x * blockDim.x + threadIdx.x;
    if (i < E) atomicAdd(&g_cnt[dst[i]], 1);
}

// local scan + dinv (cnt already loaded here)
__global__ void k_scan_local(int n) {
    int b = blockIdx.x;
    int t = threadIdx.x;          // 256 threads
    int lane = t & 31, wid = t >> 5;
    int idx = b * SCAN_BLK + t * 4;
    int v0 = (idx + 0 < n) ? g_cnt[idx + 0] : 0;
    int v1 = (idx + 1 < n) ? g_cnt[idx + 1] : 0;
    int v2 = (idx + 2 < n) ? g_cnt[idx + 2] : 0;
    int v3 = (idx + 3 < n) ? g_cnt[idx + 3] : 0;
    if (idx + 0 < n) g_dinv[idx + 0] = rsqrtf((float)v0 + 1.0f);
    if (idx + 1 < n) g_dinv[idx + 1] = rsqrtf((float)v1 + 1.0f);
    if (idx + 2 < n) g_dinv[idx + 2] = rsqrtf((float)v2 + 1.0f);
    if (idx + 3 < n) g_dinv[idx + 3] = rsqrtf((float)v3 + 1.0f);
    int s = v0 + v1 + v2 + v3;
    int pre = s;
    #pragma unroll
    for (int d = 1; d < 32; d <<= 1) {
        int t2 = __shfl_up_sync(0xffffffffu, pre, d);
        if (lane >= d) pre += t2;
    }
    __shared__ int wsum[8];
    __shared__ int wexcl[8];
    if (lane == 31) wsum[wid] = pre;
    __syncthreads();
    if (t == 0) {
        int acc = 0;
        #pragma unroll
        for (int i = 0; i < 8; i++) { wexcl[i] = acc; acc += wsum[i]; }
        g_bsum[b] = acc;
    }
    __syncthreads();
    int run = (pre - s) + wexcl[wid];
    if (idx + 0 < n) g_off[idx + 0] = run;  run += v0;
    if (idx + 1 < n) g_off[idx + 1] = run;  run += v1;
    if (idx + 2 < n) g_off[idx + 2] = run;  run += v2;
    if (idx + 3 < n) g_off[idx + 3] = run;
}

// finalize offsets (bsums scan folded in, redone per block), cursor, a1 init.
__global__ void k_scan_add(int nb, int n) {
    __shared__ int sb[MAX_SBLKS];
    __shared__ int stotal;
    int t = threadIdx.x;
    if (t < nb) sb[t] = g_bsum[t];
    __syncthreads();
    if (t == 0) {
        int acc = 0;
        for (int i = 0; i < nb; i++) { int v = sb[i]; sb[i] = acc; acc += v; }
        stotal = acc;
    }
    __syncthreads();
    int i = blockIdx.x * blockDim.x + t;
    if (i < n) {
        int o = g_off[i] + sb[i >> 10];
        g_off[i] = o;
        g_cursor[i] = o;
        float di = g_dinv[i];
        g_a1[i] = di * di;
    }
    if (blockIdx.x == 0 && t == 0) g_off[n] = stotal;
}

// fill CSR (u16 indices) + accumulate a1 (row sums of A_norm) via float atomics
__global__ void k_fill(const int* __restrict__ src, const int* __restrict__ dst, int E) {
    int e = blockIdx.x * blockDim.x + threadIdx.x;
    if (e < E) {
        int s = src[e], d = dst[e];
        float w = g_dinv[s] * g_dinv[d];
        int p = atomicAdd(&g_cursor[d], 1);
        g_eidx[p] = (unsigned short)s;
        atomicAdd(&g_a1[d], w);
    }
}

// ---------------------------------------------------------------------------
// Weight precompute (single kernel): Wem/bem, Wdd/bdd, bc
// ---------------------------------------------------------------------------
__global__ void k_wpre(const float* __restrict__ W_enc, const float* __restrict__ b_enc,
                       const float* __restrict__ W_mean, const float* __restrict__ W_lv,
                       const float* __restrict__ b_mean, const float* __restrict__ b_lv,
                       const float* __restrict__ W_d1, const float* __restrict__ b_d1,
                       const float* __restrict__ W_d2) {
    int idx = blockIdx.x * blockDim.x + threadIdx.x;
    if (idx < 129 * 128) {
        int r = idx >> 7, c = idx & 127;
        const float* arow = (r < 128) ? (W_enc + r * 128) : b_enc;
        const float* bcol = (c < 64) ? (W_mean + c) : (W_lv + (c - 64));
        float s = 0.0f;
        #pragma unroll 8
        for (int j = 0; j < 128; j++) s = fmaf(arow[j], bcol[j * 64], s);
        if (r < 128) g_Wem[r * 128 + c] = s; else g_bem[c] = s;
    } else if (idx < 129 * 128 + 65 * 128) {
        int t = idx - 129 * 128;
        int r = t >> 7, c = t & 127;
        const float* arow = (r < 64) ? (W_d1 + r * 128) : b_d1;
        float s = 0.0f;
        #pragma unroll 8
        for (int j = 0; j < 128; j++) s = fmaf(arow[j], W_d2[j * 128 + c], s);
        if (r < 64) g_Wdd[r * 128 + c] = s; else g_bdd[c] = s;
    } else if (idx < 129 * 128 + 65 * 128 + 128) {
        int c = idx - (129 * 128 + 65 * 128);
        g_bc[c] = (c < 64) ? b_mean[c] : b_lv[c - 64];
    }
}

// ---------------------------------------------------------------------------
// fp32 -> fp16 with U-scaling: H[row] = dinv[row] * X[row]
// ---------------------------------------------------------------------------
__global__ void k_f2h_scaled(const float* __restrict__ X, __half* __restrict__ H, int N) {
    int i = blockIdx.x * blockDim.x + threadIdx.x;   // over N*64 float2 groups
    if (i < N * 64) {
        int row = i >> 6;
        float di = g_dinv[row];
        float2 v = ((const float2*)X)[i];
        ((__half2*)H)[i] = __floats2half2_rn(di * v.x, di * v.y);
    }
}

// ---------------------------------------------------------------------------
// Unweighted scaled-space hops: out = scale(w) * (x[w] + sum_{s in nbr} x[s])
//   POW=2: scale = dinv^2 (between hops), POW=1: scale = dinv (final hop)
//   OUTH: half output, else fp32
// ---------------------------------------------------------------------------
__device__ __forceinline__ float4 h4_to_f4(float2 raw) {
    __half2 h0 = *reinterpret_cast<__half2*>(&raw.x);
    __half2 h1 = *reinterpret_cast<__half2*>(&raw.y);
    float2 f0 = __half22float2(h0);
    float2 f1 = __half22float2(h1);
    return make_float4(f0.x, f0.y, f1.x, f1.y);
}
__device__ __forceinline__ void add4(float4& acc, float4 a) {
    acc.x += a.x; acc.y += a.y; acc.z += a.z; acc.w += a.w;
}

template <bool OUTH, int POW>
__global__ void k_hop128(const __half* __restrict__ X, void* __restrict__ Y, int n) {
    int w = (blockIdx.x * blockDim.x + threadIdx.x) >> 5;
    int lane = threadIdx.x & 31;
    if (w >= n) return;
    const float2* Xv = (const float2*)X;   // 4 halves per float2
    float4 acc = h4_to_f4(Xv[(size_t)w * 32 + lane]);   // self loop
    int p = g_off[w], end = g_off[w + 1];
    while (p < end && (p & 7)) {
        add4(acc, h4_to_f4(Xv[(size_t)g_eidx[p] * 32 + lane]));
        p++;
    }
    for (; p + 8 <= end; p += 8) {
        uint4 iv = *(const uint4*)(g_eidx + p);   // 8 u16 indices
        int s0 = iv.x & 0xffff, s1 = iv.x >> 16;
        int s2 = iv.y & 0xffff, s3 = iv.y >> 16;
        int s4 = iv.z & 0xffff, s5 = iv.z >> 16;
        int s6 = iv.w & 0xffff, s7 = iv.w >> 16;
        float2 r0 = Xv[(size_t)s0 * 32 + lane];
        float2 r1 = Xv[(size_t)s1 * 32 + lane];
        float2 r2 = Xv[(size_t)s2 * 32 + lane];
        float2 r3 = Xv[(size_t)s3 * 32 + lane];
        float2 r4 = Xv[(size_t)s4 * 32 + lane];
        float2 r5 = Xv[(size_t)s5 * 32 + lane];
        float2 r6 = Xv[(size_t)s6 * 32 + lane];
        float2 r7 = Xv[(size_t)s7 * 32 + lane];
        add4(acc, h4_to_f4(r0)); add4(acc, h4_to_f4(r1));
        add4(acc, h4_to_f4(r2)); add4(acc, h4_to_f4(r3));
        add4(acc, h4_to_f4(r4)); add4(acc, h4_to_f4(r5));
        add4(acc, h4_to_f4(r6)); add4(acc, h4_to_f4(r7));
    }
    for (; p < end; p++)
        add4(acc, h4_to_f4(Xv[(size_t)g_eidx[p] * 32 + lane]));
    float di = g_dinv[w];
    float sc = (POW == 2) ? di * di : di;
    acc.x *= sc; acc.y *= sc; acc.z *= sc; acc.w *= sc;
    if (OUTH) {
        float2 raw;
        *reinterpret_cast<__half2*>(&raw.x) = __floats2half2_rn(acc.x, acc.y);
        *reinterpret_cast<__half2*>(&raw.y) = __floats2half2_rn(acc.z, acc.w);
        ((float2*)Y)[(size_t)w * 32 + lane] = raw;
    } else {
        ((float4*)Y)[(size_t)w * 32 + lane] = acc;
    }
}

template <bool OUTH, int POW>
__global__ void k_hop64(const __half* __restrict__ X, void* __restrict__ Y, int n) {
    int w = (blockIdx.x * blockDim.x + threadIdx.x) >> 5;
    int lane = threadIdx.x & 31;
    if (w >= n) return;
    const __half2* Xv = (const __half2*)X;
    float2 acc = __half22float2(Xv[(size_t)w * 32 + lane]);  // self loop
    int p = g_off[w], end = g_off[w + 1];
    while (p < end && (p & 7)) {
        float2 a = __half22float2(Xv[(size_t)g_eidx[p] * 32 + lane]);
        acc.x += a.x; acc.y += a.y;
        p++;
    }
    for (; p + 8 <= end; p += 8) {
        uint4 iv = *(const uint4*)(g_eidx + p);
        int s0 = iv.x & 0xffff, s1 = iv.x >> 16;
        int s2 = iv.y & 0xffff, s3 = iv.y >> 16;
        int s4 = iv.z & 0xffff, s5 = iv.z >> 16;
        int s6 = iv.w & 0xffff, s7 = iv.w >> 16;
        __half2 r0 = Xv[(size_t)s0 * 32 + lane];
        __half2 r1 = Xv[(size_t)s1 * 32 + lane];
        __half2 r2 = Xv[(size_t)s2 * 32 + lane];
        __half2 r3 = Xv[(size_t)s3 * 32 + lane];
        __half2 r4 = Xv[(size_t)s4 * 32 + lane];
        __half2 r5 = Xv[(size_t)s5 * 32 + lane];
        __half2 r6 = Xv[(size_t)s6 * 32 + lane];
        __half2 r7 = Xv[(size_t)s7 * 32 + lane];
        float2 f;
        f = __half22float2(r0); acc.x += f.x; acc.y += f.y;
        f = __half22float2(r1); acc.x += f.x; acc.y += f.y;
        f = __half22float2(r2); acc.x += f.x; acc.y += f.y;
        f = __half22float2(r3); acc.x += f.x; acc.y += f.y;
        f = __half22float2(r4); acc.x += f.x; acc.y += f.y;
        f = __half22float2(r5); acc.x += f.x; acc.y += f.y;
        f = __half22float2(r6); acc.x += f.x; acc.y += f.y;
        f = __half22float2(r7); acc.x += f.x; acc.y += f.y;
    }
    for (; p < end; p++) {
        float2 a = __half22float2(Xv[(size_t)g_eidx[p] * 32 + lane]);
        acc.x += a.x; acc.y += a.y;
    }
    float di = g_dinv[w];
    float sc = (POW == 2) ? di * di : di;
    acc.x *= sc; acc.y *= sc;
    if (OUTH) {
        ((__half2*)Y)[(size_t)w * 32 + lane] = __floats2half2_rn(acc.x, acc.y);
    } else {
        ((float2*)Y)[(size_t)w * 32 + lane] = acc;
    }
}

// ---------------------------------------------------------------------------
// Decoder GEMM, 4 rows/warp, f32x2 packed FMA: Y = X @ W + b + a1 (x) v
// ---------------------------------------------------------------------------
template <int KDIM>
__global__ void k_gemm_r1(const float* __restrict__ X, const float* __restrict__ W,
                          const float* __restrict__ b, const float* __restrict__ v,
                          float* __restrict__ Y, int M) {
    extern __shared__ float sm[];
    float* sW = sm;                 // KDIM * 128
    float* sb = sm + KDIM * 128;    // 128
    float* sv = sb + 128;           // 128
    for (int idx = threadIdx.x; idx < KDIM * 32; idx += blockDim.x)
        ((float4*)sW)[idx] = ((const float4*)W)[idx];
    if (threadIdx.x < 128) {
        sb[threadIdx.x] = b[threadIdx.x];
        sv[threadIdx.x] = v[threadIdx.x];
    }
    __syncthreads();

    const ulonglong2* sW2 = (const ulonglong2*)sW;
    int lane = threadIdx.x & 31;
    int wg = (blockIdx.x * blockDim.x + threadIdx.x) >> 5;
    int nw = (gridDim.x * blockDim.x) >> 5;
    for (int r0 = wg * 4; r0 < M; r0 += nw * 4) {
        int rr[4];
        rr[0] = r0;
        rr[1] = (r0 + 1 < M) ? r0 + 1 : r0;
        rr[2] = (r0 + 2 < M) ? r0 + 2 : r0;
        rr[3] = (r0 + 3 < M) ? r0 + 3 : r0;
        const float* xp[4];
        u64 accl[4], acch[4];
        float4 bb = ((const float4*)sb)[lane];
        float4 vv = ((const float4*)sv)[lane];
        #pragma unroll
        for (int i = 0; i < 4; i++) {
            xp[i] = X + (size_t)rr[i] * KDIM;
            float av = g_a1[rr[i]];
            accl[i] = pack2(fmaf(av, vv.x, bb.x), fmaf(av, vv.y, bb.y));
            acch[i] = pack2(fmaf(av, vv.z, bb.z), fmaf(av, vv.w, bb.w));
        }
        #pragma unroll 4
        for (int k = 0; k < KDIM; k += 4) {
            ulonglong2 w0 = sW2[(size_t)(k + 0) * 32 + lane];
            ulonglong2 w1 = sW2[(size_t)(k + 1) * 32 + lane];
            ulonglong2 w2 = sW2[(size_t)(k + 2) * 32 + lane];
            ulonglong2 w3 = sW2[(size_t)(k + 3) * 32 + lane];
            #pragma unroll
            for (int i = 0; i < 4; i++) {
                float4 a = *(const float4*)(xp[i] + k);
                u64 s;
                s = bcast2(a.x); fmaa2(accl[i], s, w0.x); fmaa2(acch[i], s, w0.y);
                s = bcast2(a.y); fmaa2(accl[i], s, w1.x); fmaa2(acch[i], s, w1.y);
                s = bcast2(a.z); fmaa2(accl[i], s, w2.x); fmaa2(acch[i], s, w2.y);
                s = bcast2(a.w); fmaa2(accl[i], s, w3.x); fmaa2(acch[i], s, w3.y);
            }
        }
        #pragma unroll
        for (int i = 0; i < 4; i++) {
            if (r0 + i < M) {
                float2 o0 = unpack2(accl[i]), o1 = unpack2(acch[i]);
                *(float4*)(Y + (size_t)(r0 + i) * 128 + lane * 4) =
                    make_float4(o0.x, o0.y, o1.x, o1.y);
            }
        }
    }
}

// ---------------------------------------------------------------------------
// Encoder GEMM with fused reparameterization epilogue.
//   zh = dinv[r] * z   (scaled-space half copy for decoder hop1)
// ---------------------------------------------------------------------------
__global__ void k_gemm_enc(const float* __restrict__ X, const float* __restrict__ W,
                           const float* __restrict__ b, const float* __restrict__ v,
                           const float* __restrict__ noise,
                           float* __restrict__ z, float* __restrict__ m,
                           float* __restrict__ lv, __half* __restrict__ zh, int M) {
    extern __shared__ float sm[];
    float* sW = sm;                 // 128 * 128
    float* sb = sm + 128 * 128;     // 128
    float* sv = sb + 128;           // 128
    for (int idx = threadIdx.x; idx < 128 * 32; idx += blockDim.x)
        ((float4*)sW)[idx] = ((const float4*)W)[idx];
    if (threadIdx.x < 128) {
        sb[threadIdx.x] = b[threadIdx.x];
        sv[threadIdx.x] = v[threadIdx.x];
    }
    __syncthreads();

    const ulonglong2* sW2 = (const ulonglong2*)sW;
    int lane = threadIdx.x & 31;
    int wg = (blockIdx.x * blockDim.x + threadIdx.x) >> 5;
    int nw = (gridDim.x * blockDim.x) >> 5;
    for (int r0 = wg * 4; r0 < M; r0 += nw * 4) {
        int rr[4];
        rr[0] = r0;
        rr[1] = (r0 + 1 < M) ? r0 + 1 : r0;
        rr[2] = (r0 + 2 < M) ? r0 + 2 : r0;
        rr[3] = (r0 + 3 < M) ? r0 + 3 : r0;
        const float* xp[4];
        u64 accl[4], acch[4];
        float4 bb = ((const float4*)sb)[lane];
        float4 vv = ((const float4*)sv)[lane];
        #pragma unroll
        for (int i = 0; i < 4; i++) {
            xp[i] = X + (size_t)rr[i] * 128;
            float av = g_a1[rr[i]];
            accl[i] = pack2(fmaf(av, vv.x, bb.x), fmaf(av, vv.y, bb.y));
            acch[i] = pack2(fmaf(av, vv.z, bb.z), fmaf(av, vv.w, bb.w));
        }
        #pragma unroll 4
        for (int k = 0; k < 128; k += 4) {
            ulonglong2 w0 = sW2[(size_t)(k + 0) * 32 + lane];
            ulonglong2 w1 = sW2[(size_t)(k + 1) * 32 + lane];
            ulonglong2 w2 = sW2[(size_t)(k + 2) * 32 + lane];
            ulonglong2 w3 = sW2[(size_t)(k + 3) * 32 + lane];
            #pragma unroll
            for (int i = 0; i < 4; i++) {
                float4 a = *(const float4*)(xp[i] + k);
                u64 s;
                s = bcast2(a.x); fmaa2(accl[i], s, w0.x); fmaa2(acch[i], s, w0.y);
                s = bcast2(a.y); fmaa2(accl[i], s, w1.x); fmaa2(acch[i], s, w1.y);
                s = bcast2(a.z); fmaa2(accl[i], s, w2.x); fmaa2(acch[i], s, w2.y);
                s = bcast2(a.w); fmaa2(accl[i], s, w3.x); fmaa2(acch[i], s, w3.y);
            }
        }
        #pragma unroll
        for (int i = 0; i < 4; i++) {
            int r = r0 + i;
            if (r >= M) break;   // uniform across warp
            float2 lo = unpack2(accl[i]), hi = unpack2(acch[i]);
            float4 val = make_float4(lo.x, lo.y, hi.x, hi.y);
            float4 pv;
            pv.x = __shfl_xor_sync(0xffffffffu, val.x, 16);
            pv.y = __shfl_xor_sync(0xffffffffu, val.y, 16);
            pv.z = __shfl_xor_sync(0xffffffffu, val.z, 16);
            pv.w = __shfl_xor_sync(0xffffffffu, val.w, 16);
            if (lane < 16) {
                ((float4*)m)[(size_t)r * 16 + lane] = val;
                float4 nz = ((const float4*)noise)[(size_t)r * 16 + lane];
                float4 zz;
                zz.x = fmaf(nz.x, expf(0.5f * pv.x), val.x);
                zz.y = fmaf(nz.y, expf(0.5f * pv.y), val.y);
                zz.z = fmaf(nz.z, expf(0.5f * pv.z), val.z);
                zz.w = fmaf(nz.w, expf(0.5f * pv.w), val.w);
                ((float4*)z)[(size_t)r * 16 + lane] = zz;
                float di = g_dinv[r];
                float2 raw;
                *reinterpret_cast<__half2*>(&raw.x) = __floats2half2_rn(di * zz.x, di * zz.y);
                *reinterpret_cast<__half2*>(&raw.y) = __floats2half2_rn(di * zz.z, di * zz.w);
                ((float2*)zh)[(size_t)r * 16 + lane] = raw;
            } else {
                ((float4*)lv)[(size_t)r * 16 + (lane - 16)] = val;
            }
        }
    }
}

// ---------------------------------------------------------------------------
extern "C" void kernel_launch(void* const* d_in, const int* in_sizes, int n_in,
                              void* d_out, int out_size) {
    const float* feature = (const float*)d_in[0];
    const int*   ei      = (const int*)d_in[1];
    const float* noise   = (const float*)d_in[2];
    const float* W_enc   = (const float*)d_in[3];
    const float* b_enc   = (const float*)d_in[4];
    const float* W_mean  = (const float*)d_in[5];
    const float* b_mean  = (const float*)d_in[6];
    const float* W_lv    = (const float*)d_in[7];
    const float* b_lv    = (const float*)d_in[8];
    const float* W_d1    = (const float*)d_in[9];
    const float* b_d1    = (const float*)d_in[10];
    const float* W_d2    = (const float*)d_in[11];
    const float* b_d2    = (const float*)d_in[12];

    int N = in_sizes[0] / 128;
    int E = in_sizes[1] / 2;
    const int* src = ei;
    const int* dst = ei + E;

    float* zout  = (float*)d_out;
    float* mout  = zout + (size_t)N * 64;
    float* lvout = mout + (size_t)N * 64;
    float* oout  = lvout + (size_t)N * 64;

    float *bufA, *Wem, *bem, *Wdd, *bdd, *bc, *cntp;
    __half *hA, *hB;
    cudaGetSymbolAddress((void**)&cntp, g_cnt);
    cudaGetSymbolAddress((void**)&bufA, g_bufA);
    cudaGetSymbolAddress((void**)&hA, g_hA);
    cudaGetSymbolAddress((void**)&hB, g_hB);
    cudaGetSymbolAddress((void**)&Wem, g_Wem);
    cudaGetSymbolAddress((void**)&bem, g_bem);
    cudaGetSymbolAddress((void**)&Wdd, g_Wdd);
    cudaGetSymbolAddress((void**)&bdd, g_bdd);
    cudaGetSymbolAddress((void**)&bc, g_bc);

    const int smem128r = 128 * 128 * 4 + 1024;
    const int smem64r  = 64 * 128 * 4 + 1024;
    cudaFuncSetAttribute(k_gemm_enc,    cudaFuncAttributeMaxDynamicSharedMemorySize, smem128r);
    cudaFuncSetAttribute(k_gemm_r1<64>, cudaFuncAttributeMaxDynamicSharedMemorySize, smem64r);

    int tb = 256;
    int nBlkN = (N + tb - 1) / tb;
    int nBlkE = (E + tb - 1) / tb;
    int nBlkW = (N * 32 + tb - 1) / tb;   // warp per node
    int nSBlks = (N + SCAN_BLK - 1) / SCAN_BLK;
    int gemmBlocks = 444;

    // --- CSR build ---
    cudaMemsetAsync(cntp, 0, (size_t)N * sizeof(int));
    k_count<<<nBlkE, tb>>>(dst, E);
    k_scan_local<<<nSBlks, 256>>>(N);
    k_scan_add<<<nBlkN, tb>>>(nSBlks, N);
    k_fill<<<nBlkE, tb>>>(src, dst, E);

    // --- weight precompute ---
    k_wpre<<<(129 * 128 + 65 * 128 + 128 + tb - 1) / tb, tb>>>(
        W_enc, b_enc, W_mean, W_lv, b_mean, b_lv, W_d1, b_d1, W_d2);

    // --- encoder: AAf = U Ā U² Ā (U f);  [mean|lv] = (AAf) Wem + a1 (x) bem + bc ---
    k_f2h_scaled<<<(N * 64 + tb - 1) / tb, tb>>>(feature, hA, N);
    k_hop128<true, 2><<<nBlkW, tb>>>(hA, hB, N);
    k_hop128<false, 1><<<nBlkW, tb>>>(hB, bufA, N);
    k_gemm_enc<<<gemmBlocks, tb, smem128r>>>(bufA, Wem, bc, bem, noise,
                                             zout, mout, lvout, hA, N);

    // --- decoder: AAz from zh = U z;  out = (AAz) Wdd + a1 (x) bdd + bd2 ---
    k_hop64<true, 2><<<nBlkW, tb>>>(hA, hB, N);
    k_hop64<false, 1><<<nBlkW, tb>>>(hB, bufA, N);
    k_gemm_r1<64><<<gemmBlocks, tb, smem64r>>>(bufA, Wdd, b_d2, bdd, oout, N);
}